// round 1
// baseline (speedup 1.0000x reference)
#include <cuda_runtime.h>
#include <math.h>

#define SEQ 4096
#define CH  512
#define NB  2
#define NH  8
#define HD  64
#define CPG 16        // channels per group (512/32)
#define NGB 64        // total (batch, group) pairs

// ---------------- scratch (global device arrays; no runtime allocation) ----
__device__ float g_hs[NB * CH * SEQ];   // groupnormed x, layout [b][c][s]
__device__ float g_q [NB * CH * SEQ];   // [b][h*64+d][s], pre-scaled by 1/8
__device__ float g_k [NB * CH * SEQ];   // [b][h*64+d][s]
__device__ float g_v [NB * CH * SEQ];   // [b][h*64+d][s]
__device__ float g_o [NB * CH * SEQ];   // attention output, [b][h*64+d][s]
__device__ float g_stats[NGB * 2];      // mean, rstd per (b,group)

// ---------------- GroupNorm: stats -----------------------------------------
__global__ __launch_bounds__(256) void gn_stats(const float* __restrict__ x) {
    int bg = blockIdx.x;                       // b*32 + g
    const float* p = x + (size_t)bg * CPG * SEQ;
    int tid = threadIdx.x;
    float s = 0.f, s2 = 0.f;
    for (int i = tid; i < CPG * SEQ; i += 256) {
        float v = p[i];
        s += v; s2 += v * v;
    }
    __shared__ float ss[256], sq[256];
    ss[tid] = s; sq[tid] = s2;
    __syncthreads();
    for (int st = 128; st > 0; st >>= 1) {
        if (tid < st) { ss[tid] += ss[tid + st]; sq[tid] += sq[tid + st]; }
        __syncthreads();
    }
    if (tid == 0) {
        float inv_n = 1.0f / (float)(CPG * SEQ);
        float mean = ss[0] * inv_n;
        float var  = sq[0] * inv_n - mean * mean;
        g_stats[bg * 2 + 0] = mean;
        g_stats[bg * 2 + 1] = rsqrtf(var + 1e-5f);
    }
}

// ---------------- GroupNorm: apply (writes g_hs, layout [b][c][s]) ---------
__global__ __launch_bounds__(256) void gn_apply(const float* __restrict__ x,
                                                const float* __restrict__ w,
                                                const float* __restrict__ bsc) {
    int idx = blockIdx.x * 256 + threadIdx.x;          // float4 index
    int e   = idx * 4;
    int c   = (e / SEQ) & (CH - 1);
    int bg  = e >> 16;                                 // e / (CPG*SEQ)
    float mean = g_stats[bg * 2 + 0];
    float rstd = g_stats[bg * 2 + 1];
    float sw = w[c] * rstd;
    float sb = bsc[c] - mean * sw;
    float4 xv = ((const float4*)x)[idx];
    float4 o;
    o.x = xv.x * sw + sb; o.y = xv.y * sw + sb;
    o.z = xv.z * sw + sb; o.w = xv.w * sw + sb;
    ((float4*)g_hs)[idx] = o;
}

// ---------------- QKV GEMM: C[j][s] = W[j][c] * hs[c][s] + bias ------------
// grid: (32 s-blocks, 12 j-blocks, 2 batches), 128x128 tile, K-tile 8
__global__ __launch_bounds__(256) void qkv_gemm(const float* __restrict__ wq,
                                                const float* __restrict__ bq,
                                                const float* __restrict__ wkv,
                                                const float* __restrict__ bkv) {
    int sb = blockIdx.x, jb = blockIdx.y, b = blockIdx.z;
    int jbase = jb * 128;

    const float* A; const float* bias; float* dst; float scale;
    if (jb < 4)      { A = wq  + (size_t)jbase * CH;          bias = bq  + jbase;         dst = g_q; scale = 0.125f; }
    else             { A = wkv + (size_t)(jbase - 512) * CH;  bias = bkv + (jbase - 512); dst = (jb < 8) ? g_k : g_v; scale = 1.0f; }
    int jloc = jbase & 511;
    const float* Bm = g_hs + (size_t)b * CH * SEQ;
    dst += (size_t)b * CH * SEQ;

    __shared__ float As[8][128];
    __shared__ float Bs[8][128];

    int tid = threadIdx.x;
    int ty = tid >> 4, tx = tid & 15;
    int arow = tid >> 1, ac4 = (tid & 1) * 4;
    int brow = tid >> 5, bc4 = (tid & 31) * 4;

    float acc[8][8];
#pragma unroll
    for (int i = 0; i < 8; i++)
#pragma unroll
        for (int j = 0; j < 8; j++) acc[i][j] = 0.f;

    for (int kt = 0; kt < CH; kt += 8) {
        float4 a4 = *(const float4*)&A[(size_t)arow * CH + kt + ac4];
        float4 b4 = *(const float4*)&Bm[(size_t)(kt + brow) * SEQ + sb * 128 + bc4];
        __syncthreads();
        As[ac4 + 0][arow] = a4.x; As[ac4 + 1][arow] = a4.y;
        As[ac4 + 2][arow] = a4.z; As[ac4 + 3][arow] = a4.w;
        *(float4*)&Bs[brow][bc4] = b4;
        __syncthreads();
#pragma unroll
        for (int kk = 0; kk < 8; kk++) {
            float4 a0 = *(float4*)&As[kk][ty * 8];
            float4 a1 = *(float4*)&As[kk][ty * 8 + 4];
            float4 b0 = *(float4*)&Bs[kk][tx * 8];
            float4 b1 = *(float4*)&Bs[kk][tx * 8 + 4];
            float av[8] = {a0.x, a0.y, a0.z, a0.w, a1.x, a1.y, a1.z, a1.w};
            float bv[8] = {b0.x, b0.y, b0.z, b0.w, b1.x, b1.y, b1.z, b1.w};
#pragma unroll
            for (int i = 0; i < 8; i++)
#pragma unroll
                for (int j = 0; j < 8; j++) acc[i][j] += av[i] * bv[j];
        }
    }
#pragma unroll
    for (int i = 0; i < 8; i++) {
        float bb = bias[ty * 8 + i];
        size_t rowoff = (size_t)(jloc + ty * 8 + i) * SEQ + sb * 128 + tx * 8;
#pragma unroll
        for (int j4 = 0; j4 < 8; j4 += 4) {
            float4 o;
            o.x = (acc[i][j4 + 0] + bb) * scale;
            o.y = (acc[i][j4 + 1] + bb) * scale;
            o.z = (acc[i][j4 + 2] + bb) * scale;
            o.w = (acc[i][j4 + 3] + bb) * scale;
            *(float4*)&dst[rowoff + j4] = o;
        }
    }
}

// ---------------- Flash attention, fp32 ------------------------------------
#define QPAD 132
#define KPAD 68
#define VPAD 65
#define PPAD 65
#define ATTN_SMEM_FLOATS (64 * QPAD + 64 * KPAD + 64 * VPAD + 128 * PPAD)
#define ATTN_SMEM_BYTES  (ATTN_SMEM_FLOATS * 4)

__global__ __launch_bounds__(256) void attn_kernel() {
    int qb = blockIdx.x;        // query chunk 0..31
    int bh = blockIdx.y;        // b*8+h, 0..15
    extern __shared__ float sm[];
    float* Qs = sm;                       // [64][QPAD]  (Q^T: [d][s])
    float* Ks = Qs + 64 * QPAD;           // [64][KPAD]  ([d][t])
    float* Vs = Ks + 64 * KPAD;           // [64][VPAD]  ([d][t])
    float* Ps = Vs + 64 * VPAD;           // [128][PPAD] ([s][t])

    int tid = threadIdx.x;
    const float* qp = g_q + (size_t)bh * HD * SEQ;
    const float* kp = g_k + (size_t)bh * HD * SEQ;
    const float* vp = g_v + (size_t)bh * HD * SEQ;
    int s0 = qb * 128;

    // load Q tile: 64 d rows x 128 s
    for (int i = tid; i < 64 * 32; i += 256) {
        int d = i >> 5, sc = (i & 31) << 2;
        float4 v4 = *(const float4*)&qp[(size_t)d * SEQ + s0 + sc];
        *(float4*)&Qs[d * QPAD + sc] = v4;
    }

    int sy = tid >> 3, tx = tid & 7;   // 32 x 8 thread grid; rows sy*4.., cols tx*8..
    float m[4], l[4], O[4][8];
#pragma unroll
    for (int i = 0; i < 4; i++) {
        m[i] = -1e30f; l[i] = 0.f;
#pragma unroll
        for (int j = 0; j < 8; j++) O[i][j] = 0.f;
    }

    for (int kt = 0; kt < 64; kt++) {
        int t0 = kt * 64;
        __syncthreads();
        // load K/V tiles: 64 d x 64 t
        for (int i = tid; i < 64 * 16; i += 256) {
            int d = i >> 4, tc = (i & 15) << 2;
            float4 k4 = *(const float4*)&kp[(size_t)d * SEQ + t0 + tc];
            float4 v4 = *(const float4*)&vp[(size_t)d * SEQ + t0 + tc];
            *(float4*)&Ks[d * KPAD + tc] = k4;
            Vs[d * VPAD + tc + 0] = v4.x; Vs[d * VPAD + tc + 1] = v4.y;
            Vs[d * VPAD + tc + 2] = v4.z; Vs[d * VPAD + tc + 3] = v4.w;
        }
        __syncthreads();

        // S = (Q * 1/8) K^T : each thread 4x8
        float sacc[4][8];
#pragma unroll
        for (int i = 0; i < 4; i++)
#pragma unroll
            for (int j = 0; j < 8; j++) sacc[i][j] = 0.f;

        for (int d = 0; d < 64; d++) {
            float4 q4 = *(float4*)&Qs[d * QPAD + (sy << 2)];
            float4 k0 = *(float4*)&Ks[d * KPAD + (tx << 3)];
            float4 k1 = *(float4*)&Ks[d * KPAD + (tx << 3) + 4];
            float qv[4] = {q4.x, q4.y, q4.z, q4.w};
            float kv[8] = {k0.x, k0.y, k0.z, k0.w, k1.x, k1.y, k1.z, k1.w};
#pragma unroll
            for (int i = 0; i < 4; i++)
#pragma unroll
                for (int j = 0; j < 8; j++) sacc[i][j] += qv[i] * kv[j];
        }

        // online softmax per row; 8-lane groups share a row set
#pragma unroll
        for (int i = 0; i < 4; i++) {
            float rmax = sacc[i][0];
#pragma unroll
            for (int j = 1; j < 8; j++) rmax = fmaxf(rmax, sacc[i][j]);
#pragma unroll
            for (int off = 1; off < 8; off <<= 1)
                rmax = fmaxf(rmax, __shfl_xor_sync(0xffffffffu, rmax, off));
            float newm = fmaxf(m[i], rmax);
            float alpha = __expf(m[i] - newm);
            float rsum = 0.f;
#pragma unroll
            for (int j = 0; j < 8; j++) {
                float p = __expf(sacc[i][j] - newm);
                sacc[i][j] = p;
                rsum += p;
            }
#pragma unroll
            for (int off = 1; off < 8; off <<= 1)
                rsum += __shfl_xor_sync(0xffffffffu, rsum, off);
            l[i] = l[i] * alpha + rsum;
            m[i] = newm;
#pragma unroll
            for (int j = 0; j < 8; j++) O[i][j] *= alpha;
            // stage P
#pragma unroll
            for (int j = 0; j < 8; j++)
                Ps[(sy * 4 + i) * PPAD + tx * 8 + j] = sacc[i][j];
        }
        __syncthreads();

        // O += P V  (sum over t)
        for (int t = 0; t < 64; t++) {
            float pv[4], vv[8];
#pragma unroll
            for (int i = 0; i < 4; i++) pv[i] = Ps[(sy * 4 + i) * PPAD + t];
#pragma unroll
            for (int j = 0; j < 8; j++) vv[j] = Vs[(tx * 8 + j) * VPAD + t];
#pragma unroll
            for (int i = 0; i < 4; i++)
#pragma unroll
                for (int j = 0; j < 8; j++) O[i][j] += pv[i] * vv[j];
        }
    }

    // epilogue: normalize and write [b][j][s]
    float* op = g_o + (size_t)bh * HD * SEQ;
#pragma unroll
    for (int i = 0; i < 4; i++) {
        float inv = 1.0f / l[i];
#pragma unroll
        for (int j = 0; j < 8; j++)
            op[(size_t)(tx * 8 + j) * SEQ + s0 + sy * 4 + i] = O[i][j] * inv;
    }
}

// ---------------- Proj GEMM + bias + residual ------------------------------
// out[b][cc][s] = sum_j wproj[cc][j] * g_o[b][j][s] + bproj[cc] + x[b][cc][s]
__global__ __launch_bounds__(256) void proj_gemm(const float* __restrict__ wproj,
                                                 const float* __restrict__ bproj,
                                                 const float* __restrict__ x,
                                                 float* __restrict__ out) {
    int sb = blockIdx.x, cb = blockIdx.y, b = blockIdx.z;
    const float* A  = wproj + (size_t)cb * 128 * CH;
    const float* Bm = g_o + (size_t)b * CH * SEQ;

    __shared__ float As[8][128];
    __shared__ float Bs[8][128];

    int tid = threadIdx.x;
    int ty = tid >> 4, tx = tid & 15;
    int arow = tid >> 1, ac4 = (tid & 1) * 4;
    int brow = tid >> 5, bc4 = (tid & 31) * 4;

    float acc[8][8];
#pragma unroll
    for (int i = 0; i < 8; i++)
#pragma unroll
        for (int j = 0; j < 8; j++) acc[i][j] = 0.f;

    for (int kt = 0; kt < CH; kt += 8) {
        float4 a4 = *(const float4*)&A[(size_t)arow * CH + kt + ac4];
        float4 b4 = *(const float4*)&Bm[(size_t)(kt + brow) * SEQ + sb * 128 + bc4];
        __syncthreads();
        As[ac4 + 0][arow] = a4.x; As[ac4 + 1][arow] = a4.y;
        As[ac4 + 2][arow] = a4.z; As[ac4 + 3][arow] = a4.w;
        *(float4*)&Bs[brow][bc4] = b4;
        __syncthreads();
#pragma unroll
        for (int kk = 0; kk < 8; kk++) {
            float4 a0 = *(float4*)&As[kk][ty * 8];
            float4 a1 = *(float4*)&As[kk][ty * 8 + 4];
            float4 b0 = *(float4*)&Bs[kk][tx * 8];
            float4 b1 = *(float4*)&Bs[kk][tx * 8 + 4];
            float av[8] = {a0.x, a0.y, a0.z, a0.w, a1.x, a1.y, a1.z, a1.w};
            float bv[8] = {b0.x, b0.y, b0.z, b0.w, b1.x, b1.y, b1.z, b1.w};
#pragma unroll
            for (int i = 0; i < 8; i++)
#pragma unroll
                for (int j = 0; j < 8; j++) acc[i][j] += av[i] * bv[j];
        }
    }
#pragma unroll
    for (int i = 0; i < 8; i++) {
        int cc = cb * 128 + ty * 8 + i;
        float bb = bproj[cc];
        size_t rowoff = ((size_t)b * CH + cc) * SEQ + sb * 128 + tx * 8;
#pragma unroll
        for (int j4 = 0; j4 < 8; j4 += 4) {
            float4 r = *(const float4*)&x[rowoff + j4];
            float4 o;
            o.x = acc[i][j4 + 0] + bb + r.x;
            o.y = acc[i][j4 + 1] + bb + r.y;
            o.z = acc[i][j4 + 2] + bb + r.z;
            o.w = acc[i][j4 + 3] + bb + r.w;
            *(float4*)&out[rowoff + j4] = o;
        }
    }
}

// ---------------- launch ----------------------------------------------------
extern "C" void kernel_launch(void* const* d_in, const int* in_sizes, int n_in,
                              void* d_out, int out_size) {
    const float* x     = (const float*)d_in[0];
    const float* gnw   = (const float*)d_in[1];
    const float* gnb   = (const float*)d_in[2];
    const float* wq    = (const float*)d_in[3];
    const float* bq    = (const float*)d_in[4];
    const float* wkv   = (const float*)d_in[5];
    const float* bkv   = (const float*)d_in[6];
    const float* wproj = (const float*)d_in[7];
    const float* bproj = (const float*)d_in[8];
    float* out = (float*)d_out;

    cudaFuncSetAttribute(attn_kernel, cudaFuncAttributeMaxDynamicSharedMemorySize,
                         ATTN_SMEM_BYTES);

    gn_stats<<<NGB, 256>>>(x);
    gn_apply<<<(NB * CH * SEQ) / (256 * 4), 256>>>(x, gnw, gnb);
    qkv_gemm<<<dim3(32, 12, NB), 256>>>(wq, bq, wkv, bkv);
    attn_kernel<<<dim3(32, NH * NB), 256, ATTN_SMEM_BYTES>>>();
    proj_gemm<<<dim3(32, 4, NB), 256>>>(wproj, bproj, x, out);
}

// round 2
// speedup vs baseline: 3.3244x; 3.3244x over previous
#include <cuda_runtime.h>
#include <math.h>

#define SEQ 4096
#define CH  512
#define NB  2
#define NH  8
#define HD  64
#define CPG 16
#define NGB 64

// ---------------- scratch ----------------------------------------------------
__device__ float g_hs[NB * CH * SEQ];   // groupnormed x (tf32-rounded), [b][c][s]
__device__ float g_q [NB * CH * SEQ];   // [b][h*64+d][s], pre-scaled by 1/8, tf32
__device__ float g_k [NB * CH * SEQ];   // tf32
__device__ float g_v [NB * CH * SEQ];   // tf32
__device__ float g_o [NB * CH * SEQ];   // attention output, tf32
__device__ float g_stats[NGB * 2];
__device__ float g_wqkv_t[1536 * 512];  // [wq rows 0-511 | wkv rows 0-1023], tf32
__device__ float g_wproj_t[512 * 512];  // tf32

// ---------------- helpers ----------------------------------------------------
__device__ __forceinline__ float tf32r(float x) {
    unsigned r;
    asm("cvt.rna.tf32.f32 %0, %1;" : "=r"(r) : "f"(x));
    return __uint_as_float(r);
}

__device__ __forceinline__ void mma8(float c[4], const unsigned a[4],
                                     unsigned b0, unsigned b1) {
    asm volatile(
        "mma.sync.aligned.m16n8k8.row.col.f32.tf32.tf32.f32 "
        "{%0,%1,%2,%3}, {%4,%5,%6,%7}, {%8,%9}, {%0,%1,%2,%3};"
        : "+f"(c[0]), "+f"(c[1]), "+f"(c[2]), "+f"(c[3])
        : "r"(a[0]), "r"(a[1]), "r"(a[2]), "r"(a[3]), "r"(b0), "r"(b1));
}

// ---------------- GroupNorm: stats -------------------------------------------
__global__ __launch_bounds__(256) void gn_stats(const float* __restrict__ x) {
    int bg = blockIdx.x;
    const float* p = x + (size_t)bg * CPG * SEQ;
    int tid = threadIdx.x;
    float s = 0.f, s2 = 0.f;
    for (int i = tid; i < CPG * SEQ; i += 256) {
        float v = p[i];
        s += v; s2 += v * v;
    }
    __shared__ float ss[256], sq[256];
    ss[tid] = s; sq[tid] = s2;
    __syncthreads();
    for (int st = 128; st > 0; st >>= 1) {
        if (tid < st) { ss[tid] += ss[tid + st]; sq[tid] += sq[tid + st]; }
        __syncthreads();
    }
    if (tid == 0) {
        float inv_n = 1.0f / (float)(CPG * SEQ);
        float mean = ss[0] * inv_n;
        float var  = sq[0] * inv_n - mean * mean;
        g_stats[bg * 2 + 0] = mean;
        g_stats[bg * 2 + 1] = rsqrtf(var + 1e-5f);
    }
}

// ---------------- GroupNorm: apply (tf32-rounded output) ---------------------
__global__ __launch_bounds__(256) void gn_apply(const float* __restrict__ x,
                                                const float* __restrict__ w,
                                                const float* __restrict__ bsc) {
    int idx = blockIdx.x * 256 + threadIdx.x;
    int e   = idx * 4;
    int c   = (e / SEQ) & (CH - 1);
    int bg  = e >> 16;
    float mean = g_stats[bg * 2 + 0];
    float rstd = g_stats[bg * 2 + 1];
    float sw = w[c] * rstd;
    float sb = bsc[c] - mean * sw;
    float4 xv = ((const float4*)x)[idx];
    float4 o;
    o.x = tf32r(xv.x * sw + sb); o.y = tf32r(xv.y * sw + sb);
    o.z = tf32r(xv.z * sw + sb); o.w = tf32r(xv.w * sw + sb);
    ((float4*)g_hs)[idx] = o;
}

// ---------------- weight conversion to tf32 ----------------------------------
__global__ __launch_bounds__(256) void cvt_weights(const float* __restrict__ wq,
                                                   const float* __restrict__ wkv,
                                                   const float* __restrict__ wproj) {
    int i = blockIdx.x * 256 + threadIdx.x;    // grid covers 524288
    if (i < 524288) g_wqkv_t[262144 + i] = tf32r(wkv[i]);
    if (i < 262144) {
        g_wqkv_t[i]  = tf32r(wq[i]);
        g_wproj_t[i] = tf32r(wproj[i]);
    }
}

// ---------------- QKV GEMM (tf32 mma): C[j][s] = W[j][c] * hs[c][s] ----------
__global__ __launch_bounds__(256, 2) void qkv_mma(const float* __restrict__ bq,
                                                  const float* __restrict__ bkv) {
    int sb = blockIdx.x, jb = blockIdx.y, b = blockIdx.z;
    const float* A  = g_wqkv_t + (size_t)jb * 128 * 512;
    const float* Bm = g_hs + (size_t)b * CH * SEQ + sb * 128;
    const float* bias; float* dst; float scale;
    if (jb < 4)      { bias = bq  + jb * 128;       dst = g_q; scale = 0.125f; }
    else if (jb < 8) { bias = bkv + (jb - 4) * 128; dst = g_k; scale = 1.0f; }
    else             { bias = bkv + (jb - 4) * 128; dst = g_v; scale = 1.0f; }
    int jloc = (jb & 3) * 128;
    dst += (size_t)b * CH * SEQ;

    __shared__ float As[128 * 20];
    __shared__ float Bs[16 * 132];

    int tid = threadIdx.x, w = tid >> 5, lane = tid & 31;
    int u = lane & 3, g = lane >> 2;
    int wm = (w >> 2) * 64, wn = (w & 3) * 32;
    int am = tid >> 2, ak4 = (tid & 3) << 2;
    int bk = tid >> 5, bc4 = (tid & 31) << 2;

    float acc[4][4][4];
#pragma unroll
    for (int mt = 0; mt < 4; mt++)
#pragma unroll
        for (int nt = 0; nt < 4; nt++)
#pragma unroll
            for (int q = 0; q < 4; q++) acc[mt][nt][q] = 0.f;

    for (int kc = 0; kc < 512; kc += 16) {
        float4 a0v = *(const float4*)&A[(size_t)am * 512 + kc + ak4];
        float4 a1v = *(const float4*)&A[(size_t)(am + 64) * 512 + kc + ak4];
        float4 b0v = *(const float4*)&Bm[(size_t)(kc + bk) * SEQ + bc4];
        float4 b1v = *(const float4*)&Bm[(size_t)(kc + bk + 8) * SEQ + bc4];
        __syncthreads();
        *(float4*)&As[am * 20 + ak4] = a0v;
        *(float4*)&As[(am + 64) * 20 + ak4] = a1v;
        *(float4*)&Bs[bk * 132 + bc4] = b0v;
        *(float4*)&Bs[(bk + 8) * 132 + bc4] = b1v;
        __syncthreads();
#pragma unroll
        for (int ks = 0; ks < 16; ks += 8) {
            unsigned af[4][4], bf[4][2];
#pragma unroll
            for (int mt = 0; mt < 4; mt++) {
                int r = wm + mt * 16 + g;
                af[mt][0] = __float_as_uint(As[r * 20 + ks + u]);
                af[mt][1] = __float_as_uint(As[(r + 8) * 20 + ks + u]);
                af[mt][2] = __float_as_uint(As[r * 20 + ks + u + 4]);
                af[mt][3] = __float_as_uint(As[(r + 8) * 20 + ks + u + 4]);
            }
#pragma unroll
            for (int nt = 0; nt < 4; nt++) {
                bf[nt][0] = __float_as_uint(Bs[(ks + u) * 132 + wn + nt * 8 + g]);
                bf[nt][1] = __float_as_uint(Bs[(ks + u + 4) * 132 + wn + nt * 8 + g]);
            }
#pragma unroll
            for (int mt = 0; mt < 4; mt++)
#pragma unroll
                for (int nt = 0; nt < 4; nt++)
                    mma8(acc[mt][nt], af[mt], bf[nt][0], bf[nt][1]);
        }
    }
#pragma unroll
    for (int mt = 0; mt < 4; mt++) {
        int r0 = wm + mt * 16 + g;
        float bb0 = bias[r0], bb1 = bias[r0 + 8];
#pragma unroll
        for (int nt = 0; nt < 4; nt++) {
            int ccol = sb * 128 + wn + nt * 8 + 2 * u;
            float2 o0, o1;
            o0.x = tf32r((acc[mt][nt][0] + bb0) * scale);
            o0.y = tf32r((acc[mt][nt][1] + bb0) * scale);
            o1.x = tf32r((acc[mt][nt][2] + bb1) * scale);
            o1.y = tf32r((acc[mt][nt][3] + bb1) * scale);
            *(float2*)&dst[(size_t)(jloc + r0) * SEQ + ccol] = o0;
            *(float2*)&dst[(size_t)(jloc + r0 + 8) * SEQ + ccol] = o1;
        }
    }
}

// ---------------- Flash attention (tf32 mma) ----------------------------------
#define ATTN_SMEM_BYTES ((2 * 64 * 68 + 128 * 68) * 4)

__global__ __launch_bounds__(256, 2) void attn_mma() {
    int qb = blockIdx.x, bh = blockIdx.y;
    extern __shared__ float sm[];
    float* Ks = sm;                   // [64 d][68]
    float* Vs = sm + 64 * 68;         // [64 d][68]
    float* QP = sm + 2 * 64 * 68;     // Q stage [64][132] then P [128][68]

    int tid = threadIdx.x, w = tid >> 5, lane = tid & 31;
    int u = lane & 3, g = lane >> 2;
    const float* qp = g_q + (size_t)bh * HD * SEQ;
    const float* kp = g_k + (size_t)bh * HD * SEQ;
    const float* vp = g_v + (size_t)bh * HD * SEQ;
    int s0 = qb * 128;

    // stage Q tile [64 d][128 s] and pull fragments into registers
    for (int i = tid; i < 64 * 32; i += 256) {
        int d = i >> 5, sc = (i & 31) << 2;
        *(float4*)&QP[d * 132 + sc] = *(const float4*)&qp[(size_t)d * SEQ + s0 + sc];
    }
    __syncthreads();
    unsigned qa[8][4];
#pragma unroll
    for (int k8 = 0; k8 < 8; k8++) {
        int k0 = k8 * 8, r = w * 16 + g;
        qa[k8][0] = __float_as_uint(QP[(k0 + u) * 132 + r]);
        qa[k8][1] = __float_as_uint(QP[(k0 + u) * 132 + r + 8]);
        qa[k8][2] = __float_as_uint(QP[(k0 + u + 4) * 132 + r]);
        qa[k8][3] = __float_as_uint(QP[(k0 + u + 4) * 132 + r + 8]);
    }

    float O[8][4];
#pragma unroll
    for (int nt = 0; nt < 8; nt++)
#pragma unroll
        for (int q = 0; q < 4; q++) O[nt][q] = 0.f;
    float m0 = -1e30f, m1 = -1e30f, l0 = 0.f, l1 = 0.f;
    float* Pw = QP + (w * 16) * 68;   // this warp's private P rows

    for (int kt = 0; kt < 64; kt++) {
        int t0 = kt * 64;
        __syncthreads();
        for (int i = tid; i < 64 * 16; i += 256) {
            int d = i >> 4, tc = (i & 15) << 2;
            *(float4*)&Ks[d * 68 + tc] = *(const float4*)&kp[(size_t)d * SEQ + t0 + tc];
            *(float4*)&Vs[d * 68 + tc] = *(const float4*)&vp[(size_t)d * SEQ + t0 + tc];
        }
        __syncthreads();

        // S = Q K^T  (Q pre-scaled by 1/8)
        float S[8][4];
#pragma unroll
        for (int nt = 0; nt < 8; nt++)
#pragma unroll
            for (int q = 0; q < 4; q++) S[nt][q] = 0.f;
#pragma unroll
        for (int k8 = 0; k8 < 8; k8++) {
            int k0 = k8 * 8;
#pragma unroll
            for (int nt = 0; nt < 8; nt++) {
                unsigned b0 = __float_as_uint(Ks[(k0 + u) * 68 + nt * 8 + g]);
                unsigned b1 = __float_as_uint(Ks[(k0 + u + 4) * 68 + nt * 8 + g]);
                mma8(S[nt], qa[k8], b0, b1);
            }
        }

        // online softmax (rows g and g+8; cols spread across quad lanes)
        float rmax0 = -1e30f, rmax1 = -1e30f;
#pragma unroll
        for (int nt = 0; nt < 8; nt++) {
            rmax0 = fmaxf(rmax0, fmaxf(S[nt][0], S[nt][1]));
            rmax1 = fmaxf(rmax1, fmaxf(S[nt][2], S[nt][3]));
        }
        rmax0 = fmaxf(rmax0, __shfl_xor_sync(0xffffffffu, rmax0, 1));
        rmax0 = fmaxf(rmax0, __shfl_xor_sync(0xffffffffu, rmax0, 2));
        rmax1 = fmaxf(rmax1, __shfl_xor_sync(0xffffffffu, rmax1, 1));
        rmax1 = fmaxf(rmax1, __shfl_xor_sync(0xffffffffu, rmax1, 2));
        float nm0 = fmaxf(m0, rmax0), nm1 = fmaxf(m1, rmax1);
        float al0 = __expf(m0 - nm0), al1 = __expf(m1 - nm1);
        float rs0 = 0.f, rs1 = 0.f;
#pragma unroll
        for (int nt = 0; nt < 8; nt++) {
            float p0 = __expf(S[nt][0] - nm0), p1 = __expf(S[nt][1] - nm0);
            float p2 = __expf(S[nt][2] - nm1), p3 = __expf(S[nt][3] - nm1);
            rs0 += p0 + p1; rs1 += p2 + p3;
            float2 w0 = make_float2(tf32r(p0), tf32r(p1));
            float2 w1 = make_float2(tf32r(p2), tf32r(p3));
            *(float2*)&Pw[g * 68 + nt * 8 + 2 * u] = w0;
            *(float2*)&Pw[(g + 8) * 68 + nt * 8 + 2 * u] = w1;
        }
        rs0 += __shfl_xor_sync(0xffffffffu, rs0, 1);
        rs0 += __shfl_xor_sync(0xffffffffu, rs0, 2);
        rs1 += __shfl_xor_sync(0xffffffffu, rs1, 1);
        rs1 += __shfl_xor_sync(0xffffffffu, rs1, 2);
        l0 = l0 * al0 + rs0; l1 = l1 * al1 + rs1;
        m0 = nm0; m1 = nm1;
#pragma unroll
        for (int nt = 0; nt < 8; nt++) {
            O[nt][0] *= al0; O[nt][1] *= al0;
            O[nt][2] *= al1; O[nt][3] *= al1;
        }
        __syncwarp();

        // O += P V
#pragma unroll
        for (int k8 = 0; k8 < 8; k8++) {
            int k0 = k8 * 8;
            unsigned pa[4];
            pa[0] = __float_as_uint(Pw[g * 68 + k0 + u]);
            pa[1] = __float_as_uint(Pw[(g + 8) * 68 + k0 + u]);
            pa[2] = __float_as_uint(Pw[g * 68 + k0 + u + 4]);
            pa[3] = __float_as_uint(Pw[(g + 8) * 68 + k0 + u + 4]);
#pragma unroll
            for (int nt = 0; nt < 8; nt++) {
                unsigned b0 = __float_as_uint(Vs[(nt * 8 + g) * 68 + k0 + u]);
                unsigned b1 = __float_as_uint(Vs[(nt * 8 + g) * 68 + k0 + u + 4]);
                mma8(O[nt], pa, b0, b1);
            }
        }
    }

    // epilogue: normalize, write [d][s] tf32-rounded
    float inv0 = 1.f / l0, inv1 = 1.f / l1;
    float* op = g_o + (size_t)bh * HD * SEQ;
    int sg = s0 + w * 16 + g;
#pragma unroll
    for (int nt = 0; nt < 8; nt++) {
        int d0 = nt * 8 + 2 * u;
        op[(size_t)d0 * SEQ + sg]           = tf32r(O[nt][0] * inv0);
        op[(size_t)(d0 + 1) * SEQ + sg]     = tf32r(O[nt][1] * inv0);
        op[(size_t)d0 * SEQ + sg + 8]       = tf32r(O[nt][2] * inv1);
        op[(size_t)(d0 + 1) * SEQ + sg + 8] = tf32r(O[nt][3] * inv1);
    }
}

// ---------------- Proj GEMM (tf32 mma) + bias + residual ---------------------
__global__ __launch_bounds__(256, 2) void proj_mma(const float* __restrict__ bproj,
                                                   const float* __restrict__ x,
                                                   float* __restrict__ out) {
    int sb = blockIdx.x, cb = blockIdx.y, b = blockIdx.z;
    const float* A  = g_wproj_t + (size_t)cb * 128 * 512;
    const float* Bm = g_o + (size_t)b * CH * SEQ + sb * 128;

    __shared__ float As[128 * 20];
    __shared__ float Bs[16 * 132];

    int tid = threadIdx.x, w = tid >> 5, lane = tid & 31;
    int u = lane & 3, g = lane >> 2;
    int wm = (w >> 2) * 64, wn = (w & 3) * 32;
    int am = tid >> 2, ak4 = (tid & 3) << 2;
    int bk = tid >> 5, bc4 = (tid & 31) << 2;

    float acc[4][4][4];
#pragma unroll
    for (int mt = 0; mt < 4; mt++)
#pragma unroll
        for (int nt = 0; nt < 4; nt++)
#pragma unroll
            for (int q = 0; q < 4; q++) acc[mt][nt][q] = 0.f;

    for (int kc = 0; kc < 512; kc += 16) {
        float4 a0v = *(const float4*)&A[(size_t)am * 512 + kc + ak4];
        float4 a1v = *(const float4*)&A[(size_t)(am + 64) * 512 + kc + ak4];
        float4 b0v = *(const float4*)&Bm[(size_t)(kc + bk) * SEQ + bc4];
        float4 b1v = *(const float4*)&Bm[(size_t)(kc + bk + 8) * SEQ + bc4];
        __syncthreads();
        *(float4*)&As[am * 20 + ak4] = a0v;
        *(float4*)&As[(am + 64) * 20 + ak4] = a1v;
        *(float4*)&Bs[bk * 132 + bc4] = b0v;
        *(float4*)&Bs[(bk + 8) * 132 + bc4] = b1v;
        __syncthreads();
#pragma unroll
        for (int ks = 0; ks < 16; ks += 8) {
            unsigned af[4][4], bf[4][2];
#pragma unroll
            for (int mt = 0; mt < 4; mt++) {
                int r = wm + mt * 16 + g;
                af[mt][0] = __float_as_uint(As[r * 20 + ks + u]);
                af[mt][1] = __float_as_uint(As[(r + 8) * 20 + ks + u]);
                af[mt][2] = __float_as_uint(As[r * 20 + ks + u + 4]);
                af[mt][3] = __float_as_uint(As[(r + 8) * 20 + ks + u + 4]);
            }
#pragma unroll
            for (int nt = 0; nt < 4; nt++) {
                bf[nt][0] = __float_as_uint(Bs[(ks + u) * 132 + wn + nt * 8 + g]);
                bf[nt][1] = __float_as_uint(Bs[(ks + u + 4) * 132 + wn + nt * 8 + g]);
            }
#pragma unroll
            for (int mt = 0; mt < 4; mt++)
#pragma unroll
                for (int nt = 0; nt < 4; nt++)
                    mma8(acc[mt][nt], af[mt], bf[nt][0], bf[nt][1]);
        }
    }
#pragma unroll
    for (int mt = 0; mt < 4; mt++) {
        int r0 = cb * 128 + wm + mt * 16 + g;
        float bb0 = bproj[r0], bb1 = bproj[r0 + 8];
#pragma unroll
        for (int nt = 0; nt < 4; nt++) {
            int ccol = sb * 128 + wn + nt * 8 + 2 * u;
            size_t off0 = ((size_t)b * CH + r0) * SEQ + ccol;
            size_t off1 = ((size_t)b * CH + r0 + 8) * SEQ + ccol;
            float2 x0 = *(const float2*)&x[off0];
            float2 x1 = *(const float2*)&x[off1];
            float2 o0, o1;
            o0.x = acc[mt][nt][0] + bb0 + x0.x;
            o0.y = acc[mt][nt][1] + bb0 + x0.y;
            o1.x = acc[mt][nt][2] + bb1 + x1.x;
            o1.y = acc[mt][nt][3] + bb1 + x1.y;
            *(float2*)&out[off0] = o0;
            *(float2*)&out[off1] = o1;
        }
    }
}

// ---------------- launch ------------------------------------------------------
extern "C" void kernel_launch(void* const* d_in, const int* in_sizes, int n_in,
                              void* d_out, int out_size) {
    const float* x     = (const float*)d_in[0];
    const float* gnw   = (const float*)d_in[1];
    const float* gnb   = (const float*)d_in[2];
    const float* wq    = (const float*)d_in[3];
    const float* bq    = (const float*)d_in[4];
    const float* wkv   = (const float*)d_in[5];
    const float* bkv   = (const float*)d_in[6];
    const float* wproj = (const float*)d_in[7];
    const float* bproj = (const float*)d_in[8];
    float* out = (float*)d_out;

    cudaFuncSetAttribute(attn_mma, cudaFuncAttributeMaxDynamicSharedMemorySize,
                         ATTN_SMEM_BYTES);

    cvt_weights<<<2048, 256>>>(wq, wkv, wproj);
    gn_stats<<<NGB, 256>>>(x);
    gn_apply<<<(NB * CH * SEQ) / (256 * 4), 256>>>(x, gnw, gnb);
    qkv_mma<<<dim3(32, 12, NB), 256>>>(bq, bkv);
    attn_mma<<<dim3(32, NH * NB), 256, ATTN_SMEM_BYTES>>>();
    proj_mma<<<dim3(32, 4, NB), 256>>>(bproj, x, out);
}

// round 3
// speedup vs baseline: 8.1863x; 2.4625x over previous
#include <cuda_runtime.h>
#include <cuda_bf16.h>
#include <math.h>

#define SEQ 4096
#define CH  512
#define NB  2

// ---------------- scratch (bf16) --------------------------------------------
__device__ __nv_bfloat16 g_hs[NB * CH * SEQ];      // [b][c][s]
__device__ __nv_bfloat16 g_q [NB * CH * SEQ];      // [b][h*64+d][s], wq pre-scaled 1/8
__device__ __nv_bfloat16 g_k [NB * CH * SEQ];
__device__ __nv_bfloat16 g_v [NB * CH * SEQ];
__device__ __nv_bfloat16 g_o [NB * SEQ * CH];      // [b][s][c]  (attention out)
__device__ __nv_bfloat16 g_wqkv[1536 * 512];       // rows 0-511 wq*0.125, 512-1535 wkv
__device__ __nv_bfloat16 g_wproj[512 * 512];
__device__ float g_sums[64 * 8 * 2];               // partial (sum,sumsq) per (bg,chunk)
__device__ float g_stats[64 * 2];                  // mean, rstd

// ---------------- helpers ----------------------------------------------------
__device__ __forceinline__ unsigned su32(const void* p) {
    return (unsigned)__cvta_generic_to_shared(p);
}
__device__ __forceinline__ void ldsm4(unsigned& a, unsigned& b, unsigned& c,
                                      unsigned& d, unsigned addr) {
    asm volatile("ldmatrix.sync.aligned.m8n8.x4.shared.b16 {%0,%1,%2,%3},[%4];"
                 : "=r"(a), "=r"(b), "=r"(c), "=r"(d) : "r"(addr));
}
__device__ __forceinline__ void ldsm4t(unsigned& a, unsigned& b, unsigned& c,
                                       unsigned& d, unsigned addr) {
    asm volatile("ldmatrix.sync.aligned.m8n8.x4.trans.shared.b16 {%0,%1,%2,%3},[%4];"
                 : "=r"(a), "=r"(b), "=r"(c), "=r"(d) : "r"(addr));
}
__device__ __forceinline__ void mmabf(float c[4], unsigned a0, unsigned a1,
                                      unsigned a2, unsigned a3,
                                      unsigned b0, unsigned b1) {
    asm volatile(
        "mma.sync.aligned.m16n8k16.row.col.f32.bf16.bf16.f32 "
        "{%0,%1,%2,%3},{%4,%5,%6,%7},{%8,%9},{%0,%1,%2,%3};"
        : "+f"(c[0]), "+f"(c[1]), "+f"(c[2]), "+f"(c[3])
        : "r"(a0), "r"(a1), "r"(a2), "r"(a3), "r"(b0), "r"(b1));
}
__device__ __forceinline__ unsigned pack2(float hi, float lo) {
    unsigned d;
    asm("cvt.rn.bf16x2.f32 %0,%1,%2;" : "=r"(d) : "f"(hi), "f"(lo));
    return d;
}

// ---------------- weight conversion ------------------------------------------
__global__ __launch_bounds__(256) void cvt_weights(const float* __restrict__ wq,
                                                   const float* __restrict__ wkv,
                                                   const float* __restrict__ wproj) {
    int i = blockIdx.x * 256 + threadIdx.x;          // 0..524287
    g_wqkv[262144 + i] = __float2bfloat16_rn(wkv[i]);
    if (i < 262144) {
        g_wqkv[i]  = __float2bfloat16_rn(wq[i] * 0.125f);
        g_wproj[i] = __float2bfloat16_rn(wproj[i]);
    }
}

// ---------------- GroupNorm: partial stats (deterministic) --------------------
__global__ __launch_bounds__(256) void gn_partial(const float* __restrict__ x) {
    int bg = blockIdx.x >> 3, chunk = blockIdx.x & 7;
    const float4* p = (const float4*)(x + (size_t)bg * 65536 + chunk * 8192);
    int tid = threadIdx.x;
    float s = 0.f, s2 = 0.f;
#pragma unroll
    for (int j = 0; j < 8; j++) {
        float4 v = p[tid + j * 256];
        s  += v.x + v.y + v.z + v.w;
        s2 += v.x * v.x + v.y * v.y + v.z * v.z + v.w * v.w;
    }
    __shared__ float ss[256], sq[256];
    ss[tid] = s; sq[tid] = s2;
    __syncthreads();
    for (int st = 128; st > 0; st >>= 1) {
        if (tid < st) { ss[tid] += ss[tid + st]; sq[tid] += sq[tid + st]; }
        __syncthreads();
    }
    if (tid == 0) {
        g_sums[blockIdx.x * 2 + 0] = ss[0];
        g_sums[blockIdx.x * 2 + 1] = sq[0];
    }
}

__global__ void gn_finalize() {
    int t = threadIdx.x;      // 64
    float s = 0.f, s2 = 0.f;
#pragma unroll
    for (int c = 0; c < 8; c++) {
        s  += g_sums[(t * 8 + c) * 2 + 0];
        s2 += g_sums[(t * 8 + c) * 2 + 1];
    }
    float inv_n = 1.0f / 65536.0f;
    float mean = s * inv_n;
    float var  = s2 * inv_n - mean * mean;
    g_stats[t * 2 + 0] = mean;
    g_stats[t * 2 + 1] = rsqrtf(var + 1e-5f);
}

// ---------------- GroupNorm apply (bf16 out) ----------------------------------
__global__ __launch_bounds__(256) void gn_apply(const float* __restrict__ x,
                                                const float* __restrict__ w,
                                                const float* __restrict__ bsc) {
    int idx = blockIdx.x * 256 + threadIdx.x;   // group of 4 elems
    int e   = idx * 4;
    int c   = (e / SEQ) & (CH - 1);
    int bg  = e >> 16;
    float mean = g_stats[bg * 2 + 0];
    float rstd = g_stats[bg * 2 + 1];
    float sw = w[c] * rstd;
    float sb = bsc[c] - mean * sw;
    float4 xv = ((const float4*)x)[idx];
    uint2 o;
    o.x = pack2(xv.y * sw + sb, xv.x * sw + sb);
    o.y = pack2(xv.w * sw + sb, xv.z * sw + sb);
    ((uint2*)g_hs)[idx] = o;
}

// ---------------- QKV GEMM (bf16 mma) -----------------------------------------
__global__ __launch_bounds__(256, 2) void qkv_mma(const float* __restrict__ bq,
                                                  const float* __restrict__ bkv) {
    int sb = blockIdx.x, jb = blockIdx.y, b = blockIdx.z;
    const __nv_bfloat16* A = g_wqkv + (size_t)jb * 128 * 512;
    const __nv_bfloat16* Bm = g_hs + (size_t)b * CH * SEQ + sb * 128;
    __nv_bfloat16* dst = (jb < 4) ? g_q : ((jb < 8) ? g_k : g_v);
    dst += (size_t)b * CH * SEQ;
    int jloc = (jb & 3) * 128;

    __shared__ __align__(16) __nv_bfloat16 As[128 * 40];
    __shared__ __align__(16) __nv_bfloat16 Bs[32 * 136];

    int tid = threadIdx.x, w = tid >> 5, lane = tid & 31;
    int u = lane & 3, g = lane >> 2, grp = lane >> 3, r = lane & 7;
    int wm = (w >> 2) * 64, wn = (w & 3) * 32;
    unsigned as0 = su32(As), bs0 = su32(Bs);

    float acc[4][4][4];
#pragma unroll
    for (int mt = 0; mt < 4; mt++)
#pragma unroll
        for (int nt = 0; nt < 4; nt++)
#pragma unroll
            for (int q = 0; q < 4; q++) acc[mt][nt][q] = 0.f;

    int a_row = tid >> 1, a_c = (tid & 1) * 16;         // A: 128 rows x 32 (2 x uint4)
    int b_row = tid >> 4, b_c = (tid & 15) * 8;         // B: 32 rows x 128

    for (int kc = 0; kc < 512; kc += 32) {
        uint4 av0 = *(const uint4*)&A[(size_t)a_row * 512 + kc + a_c];
        uint4 av1 = *(const uint4*)&A[(size_t)a_row * 512 + kc + a_c + 8];
        uint4 bv0 = *(const uint4*)&Bm[(size_t)(kc + b_row) * SEQ + b_c];
        uint4 bv1 = *(const uint4*)&Bm[(size_t)(kc + b_row + 16) * SEQ + b_c];
        __syncthreads();
        *(uint4*)&As[a_row * 40 + a_c] = av0;
        *(uint4*)&As[a_row * 40 + a_c + 8] = av1;
        *(uint4*)&Bs[b_row * 136 + b_c] = bv0;
        *(uint4*)&Bs[(b_row + 16) * 136 + b_c] = bv1;
        __syncthreads();
#pragma unroll
        for (int ks = 0; ks < 32; ks += 16) {
            unsigned af[4][4], bf[4][2];
#pragma unroll
            for (int mt = 0; mt < 4; mt++) {
                unsigned ad = as0 + ((wm + mt * 16 + (grp & 1) * 8 + r) * 40 +
                                     ks + (grp >> 1) * 8) * 2;
                ldsm4(af[mt][0], af[mt][1], af[mt][2], af[mt][3], ad);
            }
#pragma unroll
            for (int ntp = 0; ntp < 2; ntp++) {
                unsigned bd = bs0 + ((ks + (grp & 1) * 8 + r) * 136 +
                                     wn + ntp * 16 + (grp >> 1) * 8) * 2;
                ldsm4t(bf[2 * ntp][0], bf[2 * ntp][1],
                       bf[2 * ntp + 1][0], bf[2 * ntp + 1][1], bd);
            }
#pragma unroll
            for (int mt = 0; mt < 4; mt++)
#pragma unroll
                for (int nt = 0; nt < 4; nt++)
                    mmabf(acc[mt][nt], af[mt][0], af[mt][1], af[mt][2], af[mt][3],
                          bf[nt][0], bf[nt][1]);
        }
    }
    // epilogue
#pragma unroll
    for (int mt = 0; mt < 4; mt++) {
        int r0 = wm + mt * 16 + g;
        float bb0, bb1;
        if (jb < 4) { bb0 = bq[jloc + r0] * 0.125f; bb1 = bq[jloc + r0 + 8] * 0.125f; }
        else        { bb0 = bkv[(jb - 4) * 128 + r0]; bb1 = bkv[(jb - 4) * 128 + r0 + 8]; }
#pragma unroll
        for (int nt = 0; nt < 4; nt++) {
            int scol = sb * 128 + wn + nt * 8 + 2 * u;
            *(unsigned*)&dst[(size_t)(jloc + r0) * SEQ + scol] =
                pack2(acc[mt][nt][1] + bb0, acc[mt][nt][0] + bb0);
            *(unsigned*)&dst[(size_t)(jloc + r0 + 8) * SEQ + scol] =
                pack2(acc[mt][nt][3] + bb1, acc[mt][nt][2] + bb1);
        }
    }
}

// ---------------- Flash attention (bf16 mma) ------------------------------------
__global__ __launch_bounds__(256, 2) void attn_mma() {
    int qb = blockIdx.x, bh = blockIdx.y;
    __shared__ __align__(16) __nv_bfloat16 SM[64 * 136 + 2 * 64 * 72];
    __nv_bfloat16* Qs = SM;                  // [64 d][136 s]
    __nv_bfloat16* Ks = SM + 64 * 136;       // [64 d][72 t]
    __nv_bfloat16* Vs = Ks + 64 * 72;        // [64 d][72 t]

    int tid = threadIdx.x, w = tid >> 5, lane = tid & 31;
    int u = lane & 3, g = lane >> 2, grp = lane >> 3, r = lane & 7;
    const __nv_bfloat16* qp = g_q + (size_t)bh * 64 * SEQ;
    const __nv_bfloat16* kp = g_k + (size_t)bh * 64 * SEQ;
    const __nv_bfloat16* vp = g_v + (size_t)bh * 64 * SEQ;
    int s0 = qb * 128;
    unsigned qs0 = su32(Qs), ks0 = su32(Ks), vs0 = su32(Vs);

    // stage Q [64][128]
    for (int i = tid; i < 64 * 16; i += 256) {
        int d = i >> 4, c = (i & 15) * 8;
        *(uint4*)&Qs[d * 136 + c] = *(const uint4*)&qp[(size_t)d * SEQ + s0 + c];
    }
    __syncthreads();
    unsigned qa[4][4];
#pragma unroll
    for (int kd = 0; kd < 4; kd++) {
        unsigned ad = qs0 + ((kd * 16 + (grp >> 1) * 8 + r) * 136 +
                             w * 16 + (grp & 1) * 8) * 2;
        ldsm4t(qa[kd][0], qa[kd][1], qa[kd][2], qa[kd][3], ad);
    }

    float O[8][4];
#pragma unroll
    for (int nt = 0; nt < 8; nt++)
#pragma unroll
        for (int q = 0; q < 4; q++) O[nt][q] = 0.f;
    float m0 = -1e30f, m1 = -1e30f, l0 = 0.f, l1 = 0.f;

    for (int kt = 0; kt < 64; kt++) {
        int t0g = kt * 64;
        __syncthreads();
        for (int i = tid; i < 64 * 8; i += 256) {
            int d = i >> 3, c = (i & 7) * 8;
            *(uint4*)&Ks[d * 72 + c] = *(const uint4*)&kp[(size_t)d * SEQ + t0g + c];
            *(uint4*)&Vs[d * 72 + c] = *(const uint4*)&vp[(size_t)d * SEQ + t0g + c];
        }
        __syncthreads();

        // S = Q^T K
        float S[8][4];
#pragma unroll
        for (int nt = 0; nt < 8; nt++)
#pragma unroll
            for (int q = 0; q < 4; q++) S[nt][q] = 0.f;
#pragma unroll
        for (int kd = 0; kd < 4; kd++) {
#pragma unroll
            for (int ntp = 0; ntp < 4; ntp++) {
                unsigned kb0, kb1, kb2, kb3;
                unsigned ad = ks0 + ((kd * 16 + (grp & 1) * 8 + r) * 72 +
                                     ntp * 16 + (grp >> 1) * 8) * 2;
                ldsm4t(kb0, kb1, kb2, kb3, ad);
                mmabf(S[2 * ntp], qa[kd][0], qa[kd][1], qa[kd][2], qa[kd][3], kb0, kb1);
                mmabf(S[2 * ntp + 1], qa[kd][0], qa[kd][1], qa[kd][2], qa[kd][3], kb2, kb3);
            }
        }

        // online softmax (row g -> S[..][0,1], row g+8 -> S[..][2,3])
        float rmax0 = -1e30f, rmax1 = -1e30f;
#pragma unroll
        for (int nt = 0; nt < 8; nt++) {
            rmax0 = fmaxf(rmax0, fmaxf(S[nt][0], S[nt][1]));
            rmax1 = fmaxf(rmax1, fmaxf(S[nt][2], S[nt][3]));
        }
        rmax0 = fmaxf(rmax0, __shfl_xor_sync(0xffffffffu, rmax0, 1));
        rmax0 = fmaxf(rmax0, __shfl_xor_sync(0xffffffffu, rmax0, 2));
        rmax1 = fmaxf(rmax1, __shfl_xor_sync(0xffffffffu, rmax1, 1));
        rmax1 = fmaxf(rmax1, __shfl_xor_sync(0xffffffffu, rmax1, 2));
        float nm0 = fmaxf(m0, rmax0), nm1 = fmaxf(m1, rmax1);
        float al0 = __expf(m0 - nm0), al1 = __expf(m1 - nm1);
        float rs0 = 0.f, rs1 = 0.f;
#pragma unroll
        for (int nt = 0; nt < 8; nt++) {
            S[nt][0] = __expf(S[nt][0] - nm0);
            S[nt][1] = __expf(S[nt][1] - nm0);
            S[nt][2] = __expf(S[nt][2] - nm1);
            S[nt][3] = __expf(S[nt][3] - nm1);
            rs0 += S[nt][0] + S[nt][1];
            rs1 += S[nt][2] + S[nt][3];
        }
        rs0 += __shfl_xor_sync(0xffffffffu, rs0, 1);
        rs0 += __shfl_xor_sync(0xffffffffu, rs0, 2);
        rs1 += __shfl_xor_sync(0xffffffffu, rs1, 1);
        rs1 += __shfl_xor_sync(0xffffffffu, rs1, 2);
        l0 = l0 * al0 + rs0; l1 = l1 * al1 + rs1;
        m0 = nm0; m1 = nm1;
#pragma unroll
        for (int nt = 0; nt < 8; nt++) {
            O[nt][0] *= al0; O[nt][1] *= al0;
            O[nt][2] *= al1; O[nt][3] *= al1;
        }

        // O += P V  (P fragments straight from S registers)
#pragma unroll
        for (int kt4 = 0; kt4 < 4; kt4++) {
            unsigned pa0 = pack2(S[2 * kt4][1], S[2 * kt4][0]);
            unsigned pa1 = pack2(S[2 * kt4][3], S[2 * kt4][2]);
            unsigned pa2 = pack2(S[2 * kt4 + 1][1], S[2 * kt4 + 1][0]);
            unsigned pa3 = pack2(S[2 * kt4 + 1][3], S[2 * kt4 + 1][2]);
#pragma unroll
            for (int dp = 0; dp < 4; dp++) {
                unsigned vb0, vb1, vb2, vb3;
                unsigned ad = vs0 + ((dp * 16 + (grp >> 1) * 8 + r) * 72 +
                                     kt4 * 16 + (grp & 1) * 8) * 2;
                ldsm4(vb0, vb1, vb2, vb3, ad);
                mmabf(O[2 * dp], pa0, pa1, pa2, pa3, vb0, vb1);
                mmabf(O[2 * dp + 1], pa0, pa1, pa2, pa3, vb2, vb3);
            }
        }
    }

    // epilogue: normalize, transpose via smem, write g_o[b][s][c]
    __syncthreads();
    __nv_bfloat16* Os = SM;       // [128 s][72 d]
    float inv0 = 1.f / l0, inv1 = 1.f / l1;
#pragma unroll
    for (int nt = 0; nt < 8; nt++) {
        int d0 = nt * 8 + 2 * u;
        *(unsigned*)&Os[(w * 16 + g) * 72 + d0] =
            pack2(O[nt][1] * inv0, O[nt][0] * inv0);
        *(unsigned*)&Os[(w * 16 + g + 8) * 72 + d0] =
            pack2(O[nt][3] * inv1, O[nt][2] * inv1);
    }
    __syncthreads();
    int b = bh >> 3, h = bh & 7;
    __nv_bfloat16* op = g_o + ((size_t)b * SEQ) * 512 + h * 64;
    for (int i = tid; i < 128 * 8; i += 256) {
        int row = i >> 3, c = (i & 7) * 8;
        *(uint4*)&op[(size_t)(s0 + row) * 512 + c] = *(const uint4*)&Os[row * 72 + c];
    }
}

// ---------------- Proj GEMM (bf16 mma) + bias + residual ------------------------
__global__ __launch_bounds__(256, 2) void proj_mma(const float* __restrict__ bproj,
                                                   const float* __restrict__ x,
                                                   float* __restrict__ out) {
    int sb = blockIdx.x, cb = blockIdx.y, b = blockIdx.z;
    const __nv_bfloat16* A = g_wproj + (size_t)cb * 128 * 512;
    const __nv_bfloat16* Bm = g_o + ((size_t)b * SEQ + sb * 128) * 512;

    __shared__ __align__(16) __nv_bfloat16 As[128 * 40];
    __shared__ __align__(16) __nv_bfloat16 Bs[128 * 40];

    int tid = threadIdx.x, w = tid >> 5, lane = tid & 31;
    int u = lane & 3, g = lane >> 2, grp = lane >> 3, r = lane & 7;
    int wm = (w >> 2) * 64, wn = (w & 3) * 32;
    unsigned as0 = su32(As), bs0 = su32(Bs);

    float acc[4][4][4];
#pragma unroll
    for (int mt = 0; mt < 4; mt++)
#pragma unroll
        for (int nt = 0; nt < 4; nt++)
#pragma unroll
            for (int q = 0; q < 4; q++) acc[mt][nt][q] = 0.f;

    int t_row = tid >> 1, t_c = (tid & 1) * 16;

    for (int kc = 0; kc < 512; kc += 32) {
        uint4 av0 = *(const uint4*)&A[(size_t)t_row * 512 + kc + t_c];
        uint4 av1 = *(const uint4*)&A[(size_t)t_row * 512 + kc + t_c + 8];
        uint4 bv0 = *(const uint4*)&Bm[(size_t)t_row * 512 + kc + t_c];
        uint4 bv1 = *(const uint4*)&Bm[(size_t)t_row * 512 + kc + t_c + 8];
        __syncthreads();
        *(uint4*)&As[t_row * 40 + t_c] = av0;
        *(uint4*)&As[t_row * 40 + t_c + 8] = av1;
        *(uint4*)&Bs[t_row * 40 + t_c] = bv0;
        *(uint4*)&Bs[t_row * 40 + t_c + 8] = bv1;
        __syncthreads();
#pragma unroll
        for (int ks = 0; ks < 32; ks += 16) {
            unsigned af[4][4], bf[4][2];
#pragma unroll
            for (int mt = 0; mt < 4; mt++) {
                unsigned ad = as0 + ((wm + mt * 16 + (grp & 1) * 8 + r) * 40 +
                                     ks + (grp >> 1) * 8) * 2;
                ldsm4(af[mt][0], af[mt][1], af[mt][2], af[mt][3], ad);
            }
#pragma unroll
            for (int ntp = 0; ntp < 2; ntp++) {
                unsigned bd = bs0 + ((wn + ntp * 16 + (grp >> 1) * 8 + r) * 40 +
                                     ks + (grp & 1) * 8) * 2;
                ldsm4(bf[2 * ntp][0], bf[2 * ntp][1],
                      bf[2 * ntp + 1][0], bf[2 * ntp + 1][1], bd);
            }
#pragma unroll
            for (int mt = 0; mt < 4; mt++)
#pragma unroll
                for (int nt = 0; nt < 4; nt++)
                    mmabf(acc[mt][nt], af[mt][0], af[mt][1], af[mt][2], af[mt][3],
                          bf[nt][0], bf[nt][1]);
        }
    }
    // epilogue: + bias + residual, fp32 out [b][c][s]
#pragma unroll
    for (int mt = 0; mt < 4; mt++) {
        int cc0 = cb * 128 + wm + mt * 16 + g;
        float bb0 = bproj[cc0], bb1 = bproj[cc0 + 8];
#pragma unroll
        for (int nt = 0; nt < 4; nt++) {
            int scol = sb * 128 + wn + nt * 8 + 2 * u;
            size_t off0 = ((size_t)b * CH + cc0) * SEQ + scol;
            size_t off1 = ((size_t)b * CH + cc0 + 8) * SEQ + scol;
            float2 x0 = *(const float2*)&x[off0];
            float2 x1 = *(const float2*)&x[off1];
            float2 o0, o1;
            o0.x = acc[mt][nt][0] + bb0 + x0.x;
            o0.y = acc[mt][nt][1] + bb0 + x0.y;
            o1.x = acc[mt][nt][2] + bb1 + x1.x;
            o1.y = acc[mt][nt][3] + bb1 + x1.y;
            *(float2*)&out[off0] = o0;
            *(float2*)&out[off1] = o1;
        }
    }
}

// ---------------- launch --------------------------------------------------------
extern "C" void kernel_launch(void* const* d_in, const int* in_sizes, int n_in,
                              void* d_out, int out_size) {
    const float* x     = (const float*)d_in[0];
    const float* gnw   = (const float*)d_in[1];
    const float* gnb   = (const float*)d_in[2];
    const float* wq    = (const float*)d_in[3];
    const float* bq    = (const float*)d_in[4];
    const float* wkv   = (const float*)d_in[5];
    const float* bkv   = (const float*)d_in[6];
    const float* wproj = (const float*)d_in[7];
    const float* bproj = (const float*)d_in[8];
    float* out = (float*)d_out;

    cvt_weights<<<2048, 256>>>(wq, wkv, wproj);
    gn_partial<<<512, 256>>>(x);
    gn_finalize<<<1, 64>>>();
    gn_apply<<<4096, 256>>>(x, gnw, gnb);
    qkv_mma<<<dim3(32, 12, NB), 256>>>(bq, bkv);
    attn_mma<<<dim3(32, 16), 256>>>();
    proj_mma<<<dim3(32, 4, NB), 256>>>(bproj, x, out);
}

// round 4
// speedup vs baseline: 8.3104x; 1.0152x over previous
#include <cuda_runtime.h>
#include <cuda_bf16.h>
#include <math.h>

#define SEQ 4096
#define CH  512
#define NB  2

// ---------------- scratch (bf16) --------------------------------------------
__device__ __nv_bfloat16 g_hs[NB * CH * SEQ];      // [b][c][s]
__device__ __nv_bfloat16 g_q [NB * CH * SEQ];      // [b][h*64+d][s], wq pre-scaled 1/8
__device__ __nv_bfloat16 g_k [NB * CH * SEQ];
__device__ __nv_bfloat16 g_v [NB * CH * SEQ];
__device__ __nv_bfloat16 g_o [NB * SEQ * CH];      // [b][s][c]  (attention out)
__device__ __nv_bfloat16 g_wqkv[1536 * 512];       // rows 0-511 wq*0.125, 512-1535 wkv
__device__ __nv_bfloat16 g_wproj[512 * 512];
__device__ float g_sums[64 * 8 * 2];
__device__ float g_stats[64 * 2];

// ---------------- helpers ----------------------------------------------------
__device__ __forceinline__ unsigned su32(const void* p) {
    return (unsigned)__cvta_generic_to_shared(p);
}
__device__ __forceinline__ void ldsm4(unsigned& a, unsigned& b, unsigned& c,
                                      unsigned& d, unsigned addr) {
    asm volatile("ldmatrix.sync.aligned.m8n8.x4.shared.b16 {%0,%1,%2,%3},[%4];"
                 : "=r"(a), "=r"(b), "=r"(c), "=r"(d) : "r"(addr));
}
__device__ __forceinline__ void ldsm4t(unsigned& a, unsigned& b, unsigned& c,
                                       unsigned& d, unsigned addr) {
    asm volatile("ldmatrix.sync.aligned.m8n8.x4.trans.shared.b16 {%0,%1,%2,%3},[%4];"
                 : "=r"(a), "=r"(b), "=r"(c), "=r"(d) : "r"(addr));
}
__device__ __forceinline__ void mmabf(float c[4], unsigned a0, unsigned a1,
                                      unsigned a2, unsigned a3,
                                      unsigned b0, unsigned b1) {
    asm volatile(
        "mma.sync.aligned.m16n8k16.row.col.f32.bf16.bf16.f32 "
        "{%0,%1,%2,%3},{%4,%5,%6,%7},{%8,%9},{%0,%1,%2,%3};"
        : "+f"(c[0]), "+f"(c[1]), "+f"(c[2]), "+f"(c[3])
        : "r"(a0), "r"(a1), "r"(a2), "r"(a3), "r"(b0), "r"(b1));
}
__device__ __forceinline__ unsigned pack2(float hi, float lo) {
    unsigned d;
    asm("cvt.rn.bf16x2.f32 %0,%1,%2;" : "=r"(d) : "f"(hi), "f"(lo));
    return d;
}
__device__ __forceinline__ void cpa16(unsigned dst, const void* src) {
    asm volatile("cp.async.cg.shared.global [%0], [%1], 16;" :: "r"(dst), "l"(src));
}
__device__ __forceinline__ void cp_commit() {
    asm volatile("cp.async.commit_group;");
}
template <int N> __device__ __forceinline__ void cp_wait() {
    asm volatile("cp.async.wait_group %0;" :: "n"(N));
}

// ---------------- weight conversion ------------------------------------------
__global__ __launch_bounds__(256) void cvt_weights(const float* __restrict__ wq,
                                                   const float* __restrict__ wkv,
                                                   const float* __restrict__ wproj) {
    int i = blockIdx.x * 256 + threadIdx.x;          // 0..524287
    g_wqkv[262144 + i] = __float2bfloat16_rn(wkv[i]);
    if (i < 262144) {
        g_wqkv[i]  = __float2bfloat16_rn(wq[i] * 0.125f);
        g_wproj[i] = __float2bfloat16_rn(wproj[i]);
    }
}

// ---------------- GroupNorm: partial stats -------------------------------------
__global__ __launch_bounds__(256) void gn_partial(const float* __restrict__ x) {
    int bg = blockIdx.x >> 3, chunk = blockIdx.x & 7;
    const float4* p = (const float4*)(x + (size_t)bg * 65536 + chunk * 8192);
    int tid = threadIdx.x;
    float s = 0.f, s2 = 0.f;
#pragma unroll
    for (int j = 0; j < 8; j++) {
        float4 v = p[tid + j * 256];
        s  += v.x + v.y + v.z + v.w;
        s2 += v.x * v.x + v.y * v.y + v.z * v.z + v.w * v.w;
    }
    __shared__ float ss[256], sq[256];
    ss[tid] = s; sq[tid] = s2;
    __syncthreads();
    for (int st = 128; st > 0; st >>= 1) {
        if (tid < st) { ss[tid] += ss[tid + st]; sq[tid] += sq[tid + st]; }
        __syncthreads();
    }
    if (tid == 0) {
        g_sums[blockIdx.x * 2 + 0] = ss[0];
        g_sums[blockIdx.x * 2 + 1] = sq[0];
    }
}

__global__ void gn_finalize() {
    int t = threadIdx.x;      // 64
    float s = 0.f, s2 = 0.f;
#pragma unroll
    for (int c = 0; c < 8; c++) {
        s  += g_sums[(t * 8 + c) * 2 + 0];
        s2 += g_sums[(t * 8 + c) * 2 + 1];
    }
    float inv_n = 1.0f / 65536.0f;
    float mean = s * inv_n;
    float var  = s2 * inv_n - mean * mean;
    g_stats[t * 2 + 0] = mean;
    g_stats[t * 2 + 1] = rsqrtf(var + 1e-5f);
}

// ---------------- GroupNorm apply (bf16 out) ------------------------------------
__global__ __launch_bounds__(256) void gn_apply(const float* __restrict__ x,
                                                const float* __restrict__ w,
                                                const float* __restrict__ bsc) {
    int idx = blockIdx.x * 256 + threadIdx.x;
    int e   = idx * 4;
    int c   = (e / SEQ) & (CH - 1);
    int bg  = e >> 16;
    float mean = g_stats[bg * 2 + 0];
    float rstd = g_stats[bg * 2 + 1];
    float sw = w[c] * rstd;
    float sb = bsc[c] - mean * sw;
    float4 xv = ((const float4*)x)[idx];
    uint2 o;
    o.x = pack2(xv.y * sw + sb, xv.x * sw + sb);
    o.y = pack2(xv.w * sw + sb, xv.z * sw + sb);
    ((uint2*)g_hs)[idx] = o;
}

// ---------------- QKV GEMM (bf16 mma, cp.async double-buffered) -----------------
__global__ __launch_bounds__(256, 2) void qkv_mma(const float* __restrict__ bq,
                                                  const float* __restrict__ bkv) {
    int sb = blockIdx.x, jb = blockIdx.y, b = blockIdx.z;
    const __nv_bfloat16* A = g_wqkv + (size_t)jb * 128 * 512;
    const __nv_bfloat16* Bm = g_hs + (size_t)b * CH * SEQ + sb * 128;
    __nv_bfloat16* dst = (jb < 4) ? g_q : ((jb < 8) ? g_k : g_v);
    dst += (size_t)b * CH * SEQ;
    int jloc = (jb & 3) * 128;

    __shared__ __align__(16) __nv_bfloat16 As[2][128 * 40];
    __shared__ __align__(16) __nv_bfloat16 Bs[2][32 * 136];

    int tid = threadIdx.x, w = tid >> 5, lane = tid & 31;
    int u = lane & 3, g = lane >> 2, grp = lane >> 3, r = lane & 7;
    int wm = (w >> 2) * 64, wn = (w & 3) * 32;
    unsigned as0 = su32(As), bs0 = su32(Bs);

    int a_row = tid >> 1, a_c = (tid & 1) * 16;
    int b_row = tid >> 4, b_c = (tid & 15) * 8;

    float acc[4][4][4];
#pragma unroll
    for (int mt = 0; mt < 4; mt++)
#pragma unroll
        for (int nt = 0; nt < 4; nt++)
#pragma unroll
            for (int q = 0; q < 4; q++) acc[mt][nt][q] = 0.f;

    auto issue = [&](int it, int stg) {
        int kc = it * 32;
        unsigned ad = as0 + (stg * 5120 + a_row * 40 + a_c) * 2;
        cpa16(ad,      &A[(size_t)a_row * 512 + kc + a_c]);
        cpa16(ad + 16, &A[(size_t)a_row * 512 + kc + a_c + 8]);
        unsigned bd = bs0 + (stg * 4352 + b_row * 136 + b_c) * 2;
        cpa16(bd, &Bm[(size_t)(kc + b_row) * SEQ + b_c]);
        cpa16(bd + 16 * 136 * 2, &Bm[(size_t)(kc + b_row + 16) * SEQ + b_c]);
        cp_commit();
    };

    issue(0, 0);
    for (int it = 0; it < 16; it++) {
        int stg = it & 1;
        if (it < 15) { issue(it + 1, stg ^ 1); cp_wait<1>(); }
        else cp_wait<0>();
        __syncthreads();
#pragma unroll
        for (int ks = 0; ks < 32; ks += 16) {
            unsigned af[4][4], bf[4][2];
#pragma unroll
            for (int mt = 0; mt < 4; mt++) {
                unsigned ad = as0 + (stg * 5120 + (wm + mt * 16 + (grp & 1) * 8 + r) * 40 +
                                     ks + (grp >> 1) * 8) * 2;
                ldsm4(af[mt][0], af[mt][1], af[mt][2], af[mt][3], ad);
            }
#pragma unroll
            for (int ntp = 0; ntp < 2; ntp++) {
                unsigned bd = bs0 + (stg * 4352 + (ks + (grp & 1) * 8 + r) * 136 +
                                     wn + ntp * 16 + (grp >> 1) * 8) * 2;
                ldsm4t(bf[2 * ntp][0], bf[2 * ntp][1],
                       bf[2 * ntp + 1][0], bf[2 * ntp + 1][1], bd);
            }
#pragma unroll
            for (int mt = 0; mt < 4; mt++)
#pragma unroll
                for (int nt = 0; nt < 4; nt++)
                    mmabf(acc[mt][nt], af[mt][0], af[mt][1], af[mt][2], af[mt][3],
                          bf[nt][0], bf[nt][1]);
        }
        __syncthreads();
    }
    // epilogue
#pragma unroll
    for (int mt = 0; mt < 4; mt++) {
        int r0 = wm + mt * 16 + g;
        float bb0, bb1;
        if (jb < 4) { bb0 = bq[jloc + r0] * 0.125f; bb1 = bq[jloc + r0 + 8] * 0.125f; }
        else        { bb0 = bkv[(jb - 4) * 128 + r0]; bb1 = bkv[(jb - 4) * 128 + r0 + 8]; }
#pragma unroll
        for (int nt = 0; nt < 4; nt++) {
            int scol = sb * 128 + wn + nt * 8 + 2 * u;
            *(unsigned*)&dst[(size_t)(jloc + r0) * SEQ + scol] =
                pack2(acc[mt][nt][1] + bb0, acc[mt][nt][0] + bb0);
            *(unsigned*)&dst[(size_t)(jloc + r0 + 8) * SEQ + scol] =
                pack2(acc[mt][nt][3] + bb1, acc[mt][nt][2] + bb1);
        }
    }
}

// ---------------- Flash attention (bf16 mma, cp.async K/V pipeline) --------------
#define KVST (64 * 72)
#define ATTN_SMEM_BYTES ((64 * 136 + 4 * KVST) * 2)

__global__ __launch_bounds__(256, 2) void attn_mma() {
    int qb = blockIdx.x, bh = blockIdx.y;
    extern __shared__ __align__(16) __nv_bfloat16 SM[];
    __nv_bfloat16* Qs = SM;                    // [64][136]
    __nv_bfloat16* Kst = SM + 64 * 136;        // 2 stages [64][72]
    __nv_bfloat16* Vst = Kst + 2 * KVST;       // 2 stages [64][72]

    int tid = threadIdx.x, w = tid >> 5, lane = tid & 31;
    int u = lane & 3, g = lane >> 2, grp = lane >> 3, r = lane & 7;
    const __nv_bfloat16* qp = g_q + (size_t)bh * 64 * SEQ;
    const __nv_bfloat16* kp = g_k + (size_t)bh * 64 * SEQ;
    const __nv_bfloat16* vp = g_v + (size_t)bh * 64 * SEQ;
    int s0 = qb * 128;
    unsigned qs0 = su32(Qs), ks0 = su32(Kst), vs0 = su32(Vst);

    int ld_d = tid >> 2, ld_c = (tid & 3) * 16;     // 64 rows x 2 chunks

    auto issue_kv = [&](int kt, int stg) {
        int t0g = kt * 64;
        unsigned kd = ks0 + (stg * KVST + ld_d * 72 + ld_c) * 2;
        unsigned vd = vs0 + (stg * KVST + ld_d * 72 + ld_c) * 2;
        const __nv_bfloat16* kq = &kp[(size_t)ld_d * SEQ + t0g + ld_c];
        const __nv_bfloat16* vq = &vp[(size_t)ld_d * SEQ + t0g + ld_c];
        cpa16(kd, kq); cpa16(kd + 16, kq + 8);
        cpa16(vd, vq); cpa16(vd + 16, vq + 8);
        cp_commit();
    };

    issue_kv(0, 0);

    // stage Q [64][128]
    for (int i = tid; i < 64 * 16; i += 256) {
        int d = i >> 4, c = (i & 15) * 8;
        *(uint4*)&Qs[d * 136 + c] = *(const uint4*)&qp[(size_t)d * SEQ + s0 + c];
    }
    __syncthreads();
    unsigned qa[4][4];
#pragma unroll
    for (int kd = 0; kd < 4; kd++) {
        unsigned ad = qs0 + ((kd * 16 + (grp >> 1) * 8 + r) * 136 +
                             w * 16 + (grp & 1) * 8) * 2;
        ldsm4t(qa[kd][0], qa[kd][1], qa[kd][2], qa[kd][3], ad);
    }

    float O[8][4];
#pragma unroll
    for (int nt = 0; nt < 8; nt++)
#pragma unroll
        for (int q = 0; q < 4; q++) O[nt][q] = 0.f;
    float m0 = -1e30f, m1 = -1e30f, l0 = 0.f, l1 = 0.f;

    for (int kt = 0; kt < 64; kt++) {
        int stg = kt & 1;
        if (kt < 63) { issue_kv(kt + 1, stg ^ 1); cp_wait<1>(); }
        else cp_wait<0>();
        __syncthreads();

        // S = Q^T K
        float S[8][4];
#pragma unroll
        for (int nt = 0; nt < 8; nt++)
#pragma unroll
            for (int q = 0; q < 4; q++) S[nt][q] = 0.f;
#pragma unroll
        for (int kd = 0; kd < 4; kd++) {
#pragma unroll
            for (int ntp = 0; ntp < 4; ntp++) {
                unsigned kb0, kb1, kb2, kb3;
                unsigned ad = ks0 + (stg * KVST + (kd * 16 + (grp & 1) * 8 + r) * 72 +
                                     ntp * 16 + (grp >> 1) * 8) * 2;
                ldsm4t(kb0, kb1, kb2, kb3, ad);
                mmabf(S[2 * ntp], qa[kd][0], qa[kd][1], qa[kd][2], qa[kd][3], kb0, kb1);
                mmabf(S[2 * ntp + 1], qa[kd][0], qa[kd][1], qa[kd][2], qa[kd][3], kb2, kb3);
            }
        }

        // online softmax
        float rmax0 = -1e30f, rmax1 = -1e30f;
#pragma unroll
        for (int nt = 0; nt < 8; nt++) {
            rmax0 = fmaxf(rmax0, fmaxf(S[nt][0], S[nt][1]));
            rmax1 = fmaxf(rmax1, fmaxf(S[nt][2], S[nt][3]));
        }
        rmax0 = fmaxf(rmax0, __shfl_xor_sync(0xffffffffu, rmax0, 1));
        rmax0 = fmaxf(rmax0, __shfl_xor_sync(0xffffffffu, rmax0, 2));
        rmax1 = fmaxf(rmax1, __shfl_xor_sync(0xffffffffu, rmax1, 1));
        rmax1 = fmaxf(rmax1, __shfl_xor_sync(0xffffffffu, rmax1, 2));
        float nm0 = fmaxf(m0, rmax0), nm1 = fmaxf(m1, rmax1);
        float al0 = __expf(m0 - nm0), al1 = __expf(m1 - nm1);
        float rs0 = 0.f, rs1 = 0.f;
#pragma unroll
        for (int nt = 0; nt < 8; nt++) {
            S[nt][0] = __expf(S[nt][0] - nm0);
            S[nt][1] = __expf(S[nt][1] - nm0);
            S[nt][2] = __expf(S[nt][2] - nm1);
            S[nt][3] = __expf(S[nt][3] - nm1);
            rs0 += S[nt][0] + S[nt][1];
            rs1 += S[nt][2] + S[nt][3];
        }
        rs0 += __shfl_xor_sync(0xffffffffu, rs0, 1);
        rs0 += __shfl_xor_sync(0xffffffffu, rs0, 2);
        rs1 += __shfl_xor_sync(0xffffffffu, rs1, 1);
        rs1 += __shfl_xor_sync(0xffffffffu, rs1, 2);
        l0 = l0 * al0 + rs0; l1 = l1 * al1 + rs1;
        m0 = nm0; m1 = nm1;
#pragma unroll
        for (int nt = 0; nt < 8; nt++) {
            O[nt][0] *= al0; O[nt][1] *= al0;
            O[nt][2] *= al1; O[nt][3] *= al1;
        }

        // O += P V
#pragma unroll
        for (int kt4 = 0; kt4 < 4; kt4++) {
            unsigned pa0 = pack2(S[2 * kt4][1], S[2 * kt4][0]);
            unsigned pa1 = pack2(S[2 * kt4][3], S[2 * kt4][2]);
            unsigned pa2 = pack2(S[2 * kt4 + 1][1], S[2 * kt4 + 1][0]);
            unsigned pa3 = pack2(S[2 * kt4 + 1][3], S[2 * kt4 + 1][2]);
#pragma unroll
            for (int dp = 0; dp < 4; dp++) {
                unsigned vb0, vb1, vb2, vb3;
                unsigned ad = vs0 + (stg * KVST + (dp * 16 + (grp >> 1) * 8 + r) * 72 +
                                     kt4 * 16 + (grp & 1) * 8) * 2;
                ldsm4(vb0, vb1, vb2, vb3, ad);
                mmabf(O[2 * dp], pa0, pa1, pa2, pa3, vb0, vb1);
                mmabf(O[2 * dp + 1], pa0, pa1, pa2, pa3, vb2, vb3);
            }
        }
        __syncthreads();
    }

    // epilogue: normalize, transpose via smem, write g_o[b][s][c]
    __nv_bfloat16* Os = SM;       // [128 s][72 d]
    float inv0 = 1.f / l0, inv1 = 1.f / l1;
#pragma unroll
    for (int nt = 0; nt < 8; nt++) {
        int d0 = nt * 8 + 2 * u;
        *(unsigned*)&Os[(w * 16 + g) * 72 + d0] =
            pack2(O[nt][1] * inv0, O[nt][0] * inv0);
        *(unsigned*)&Os[(w * 16 + g + 8) * 72 + d0] =
            pack2(O[nt][3] * inv1, O[nt][2] * inv1);
    }
    __syncthreads();
    int b = bh >> 3, h = bh & 7;
    __nv_bfloat16* op = g_o + ((size_t)b * SEQ) * 512 + h * 64;
    for (int i = tid; i < 128 * 8; i += 256) {
        int row = i >> 3, c = (i & 7) * 8;
        *(uint4*)&op[(size_t)(s0 + row) * 512 + c] = *(const uint4*)&Os[row * 72 + c];
    }
}

// ---------------- Proj GEMM (bf16 mma, cp.async) + bias + residual ----------------
__global__ __launch_bounds__(256, 2) void proj_mma(const float* __restrict__ bproj,
                                                   const float* __restrict__ x,
                                                   float* __restrict__ out) {
    int sb = blockIdx.x, cb = blockIdx.y, b = blockIdx.z;
    const __nv_bfloat16* A = g_wproj + (size_t)cb * 128 * 512;
    const __nv_bfloat16* Bm = g_o + ((size_t)b * SEQ + sb * 128) * 512;

    __shared__ __align__(16) __nv_bfloat16 As[2][128 * 40];
    __shared__ __align__(16) __nv_bfloat16 Bs[2][128 * 40];

    int tid = threadIdx.x, w = tid >> 5, lane = tid & 31;
    int u = lane & 3, g = lane >> 2, grp = lane >> 3, r = lane & 7;
    int wm = (w >> 2) * 64, wn = (w & 3) * 32;
    unsigned as0 = su32(As), bs0 = su32(Bs);

    int t_row = tid >> 1, t_c = (tid & 1) * 16;

    float acc[4][4][4];
#pragma unroll
    for (int mt = 0; mt < 4; mt++)
#pragma unroll
        for (int nt = 0; nt < 4; nt++)
#pragma unroll
            for (int q = 0; q < 4; q++) acc[mt][nt][q] = 0.f;

    auto issue = [&](int it, int stg) {
        int kc = it * 32;
        unsigned ad = as0 + (stg * 5120 + t_row * 40 + t_c) * 2;
        unsigned bd = bs0 + (stg * 5120 + t_row * 40 + t_c) * 2;
        cpa16(ad,      &A[(size_t)t_row * 512 + kc + t_c]);
        cpa16(ad + 16, &A[(size_t)t_row * 512 + kc + t_c + 8]);
        cpa16(bd,      &Bm[(size_t)t_row * 512 + kc + t_c]);
        cpa16(bd + 16, &Bm[(size_t)t_row * 512 + kc + t_c + 8]);
        cp_commit();
    };

    issue(0, 0);
    for (int it = 0; it < 16; it++) {
        int stg = it & 1;
        if (it < 15) { issue(it + 1, stg ^ 1); cp_wait<1>(); }
        else cp_wait<0>();
        __syncthreads();
#pragma unroll
        for (int ks = 0; ks < 32; ks += 16) {
            unsigned af[4][4], bf[4][2];
#pragma unroll
            for (int mt = 0; mt < 4; mt++) {
                unsigned ad = as0 + (stg * 5120 + (wm + mt * 16 + (grp & 1) * 8 + r) * 40 +
                                     ks + (grp >> 1) * 8) * 2;
                ldsm4(af[mt][0], af[mt][1], af[mt][2], af[mt][3], ad);
            }
#pragma unroll
            for (int ntp = 0; ntp < 2; ntp++) {
                unsigned bd = bs0 + (stg * 5120 + (wn + ntp * 16 + (grp >> 1) * 8 + r) * 40 +
                                     ks + (grp & 1) * 8) * 2;
                ldsm4(bf[2 * ntp][0], bf[2 * ntp][1],
                      bf[2 * ntp + 1][0], bf[2 * ntp + 1][1], bd);
            }
#pragma unroll
            for (int mt = 0; mt < 4; mt++)
#pragma unroll
                for (int nt = 0; nt < 4; nt++)
                    mmabf(acc[mt][nt], af[mt][0], af[mt][1], af[mt][2], af[mt][3],
                          bf[nt][0], bf[nt][1]);
        }
        __syncthreads();
    }
    // epilogue: + bias + residual, fp32 out [b][c][s]
#pragma unroll
    for (int mt = 0; mt < 4; mt++) {
        int cc0 = cb * 128 + wm + mt * 16 + g;
        float bb0 = bproj[cc0], bb1 = bproj[cc0 + 8];
#pragma unroll
        for (int nt = 0; nt < 4; nt++) {
            int scol = sb * 128 + wn + nt * 8 + 2 * u;
            size_t off0 = ((size_t)b * CH + cc0) * SEQ + scol;
            size_t off1 = ((size_t)b * CH + cc0 + 8) * SEQ + scol;
            float2 x0 = *(const float2*)&x[off0];
            float2 x1 = *(const float2*)&x[off1];
            float2 o0, o1;
            o0.x = acc[mt][nt][0] + bb0 + x0.x;
            o0.y = acc[mt][nt][1] + bb0 + x0.y;
            o1.x = acc[mt][nt][2] + bb1 + x1.x;
            o1.y = acc[mt][nt][3] + bb1 + x1.y;
            *(float2*)&out[off0] = o0;
            *(float2*)&out[off1] = o1;
        }
    }
}

// ---------------- launch ----------------------------------------------------------
extern "C" void kernel_launch(void* const* d_in, const int* in_sizes, int n_in,
                              void* d_out, int out_size) {
    const float* x     = (const float*)d_in[0];
    const float* gnw   = (const float*)d_in[1];
    const float* gnb   = (const float*)d_in[2];
    const float* wq    = (const float*)d_in[3];
    const float* bq    = (const float*)d_in[4];
    const float* wkv   = (const float*)d_in[5];
    const float* bkv   = (const float*)d_in[6];
    const float* wproj = (const float*)d_in[7];
    const float* bproj = (const float*)d_in[8];
    float* out = (float*)d_out;

    cudaFuncSetAttribute(attn_mma, cudaFuncAttributeMaxDynamicSharedMemorySize,
                         ATTN_SMEM_BYTES);

    cvt_weights<<<2048, 256>>>(wq, wkv, wproj);
    gn_partial<<<512, 256>>>(x);
    gn_finalize<<<1, 64>>>();
    gn_apply<<<4096, 256>>>(x, gnw, gnb);
    qkv_mma<<<dim3(32, 12, NB), 256>>>(bq, bkv);
    attn_mma<<<dim3(32, 16), 256, ATTN_SMEM_BYTES>>>();
    proj_mma<<<dim3(32, 4, NB), 256>>>(bproj, x, out);
}

// round 6
// speedup vs baseline: 8.4775x; 1.0201x over previous
#include <cuda_runtime.h>
#include <cuda_bf16.h>
#include <math.h>

#define SEQ 4096
#define CH  512
#define NB  2
#define QS  0.18033688011112042f   // 0.125 * log2(e)

// ---------------- scratch (bf16) --------------------------------------------
__device__ __nv_bfloat16 g_hs[NB * CH * SEQ];      // [b][c][s]
__device__ __nv_bfloat16 g_q [NB * CH * SEQ];      // [b][h*64+d][s], wq pre-scaled QS
__device__ __nv_bfloat16 g_k [NB * CH * SEQ];
__device__ __nv_bfloat16 g_v [NB * CH * SEQ];
__device__ __nv_bfloat16 g_o [NB * SEQ * CH];      // [b][s][c]  (attention out)
__device__ __nv_bfloat16 g_wqkv[1536 * 512];       // rows 0-511 wq*QS, 512-1535 wkv
__device__ __nv_bfloat16 g_wproj[512 * 512];
__device__ float g_sums[64 * 8 * 2];
__device__ float g_stats[64 * 2];

// ---------------- helpers ----------------------------------------------------
__device__ __forceinline__ unsigned su32(const void* p) {
    return (unsigned)__cvta_generic_to_shared(p);
}
__device__ __forceinline__ void ldsm4(unsigned& a, unsigned& b, unsigned& c,
                                      unsigned& d, unsigned addr) {
    asm volatile("ldmatrix.sync.aligned.m8n8.x4.shared.b16 {%0,%1,%2,%3},[%4];"
                 : "=r"(a), "=r"(b), "=r"(c), "=r"(d) : "r"(addr));
}
__device__ __forceinline__ void ldsm4t(unsigned& a, unsigned& b, unsigned& c,
                                       unsigned& d, unsigned addr) {
    asm volatile("ldmatrix.sync.aligned.m8n8.x4.trans.shared.b16 {%0,%1,%2,%3},[%4];"
                 : "=r"(a), "=r"(b), "=r"(c), "=r"(d) : "r"(addr));
}
__device__ __forceinline__ void mmabf(float c[4], unsigned a0, unsigned a1,
                                      unsigned a2, unsigned a3,
                                      unsigned b0, unsigned b1) {
    asm volatile(
        "mma.sync.aligned.m16n8k16.row.col.f32.bf16.bf16.f32 "
        "{%0,%1,%2,%3},{%4,%5,%6,%7},{%8,%9},{%0,%1,%2,%3};"
        : "+f"(c[0]), "+f"(c[1]), "+f"(c[2]), "+f"(c[3])
        : "r"(a0), "r"(a1), "r"(a2), "r"(a3), "r"(b0), "r"(b1));
}
__device__ __forceinline__ unsigned pack2(float hi, float lo) {
    unsigned d;
    asm("cvt.rn.bf16x2.f32 %0,%1,%2;" : "=r"(d) : "f"(hi), "f"(lo));
    return d;
}
__device__ __forceinline__ void cpa16(unsigned dst, const void* src) {
    asm volatile("cp.async.cg.shared.global [%0], [%1], 16;" :: "r"(dst), "l"(src));
}
__device__ __forceinline__ void cp_commit() {
    asm volatile("cp.async.commit_group;");
}
template <int N> __device__ __forceinline__ void cp_wait() {
    asm volatile("cp.async.wait_group %0;" :: "n"(N));
}

// ---------------- weight conversion ------------------------------------------
__global__ __launch_bounds__(256) void cvt_weights(const float* __restrict__ wq,
                                                   const float* __restrict__ wkv,
                                                   const float* __restrict__ wproj) {
    int i = blockIdx.x * 256 + threadIdx.x;
    g_wqkv[262144 + i] = __float2bfloat16_rn(wkv[i]);
    if (i < 262144) {
        g_wqkv[i]  = __float2bfloat16_rn(wq[i] * QS);
        g_wproj[i] = __float2bfloat16_rn(wproj[i]);
    }
}

// ---------------- GroupNorm: partial stats -------------------------------------
__global__ __launch_bounds__(256) void gn_partial(const float* __restrict__ x) {
    int bg = blockIdx.x >> 3, chunk = blockIdx.x & 7;
    const float4* p = (const float4*)(x + (size_t)bg * 65536 + chunk * 8192);
    int tid = threadIdx.x;
    float s = 0.f, s2 = 0.f;
#pragma unroll
    for (int j = 0; j < 8; j++) {
        float4 v = p[tid + j * 256];
        s  += v.x + v.y + v.z + v.w;
        s2 += v.x * v.x + v.y * v.y + v.z * v.z + v.w * v.w;
    }
    __shared__ float ss[256], sq[256];
    ss[tid] = s; sq[tid] = s2;
    __syncthreads();
    for (int st = 128; st > 0; st >>= 1) {
        if (tid < st) { ss[tid] += ss[tid + st]; sq[tid] += sq[tid + st]; }
        __syncthreads();
    }
    if (tid == 0) {
        g_sums[blockIdx.x * 2 + 0] = ss[0];
        g_sums[blockIdx.x * 2 + 1] = sq[0];
    }
}

__global__ void gn_finalize() {
    int t = threadIdx.x;
    float s = 0.f, s2 = 0.f;
#pragma unroll
    for (int c = 0; c < 8; c++) {
        s  += g_sums[(t * 8 + c) * 2 + 0];
        s2 += g_sums[(t * 8 + c) * 2 + 1];
    }
    float inv_n = 1.0f / 65536.0f;
    float mean = s * inv_n;
    float var  = s2 * inv_n - mean * mean;
    g_stats[t * 2 + 0] = mean;
    g_stats[t * 2 + 1] = rsqrtf(var + 1e-5f);
}

// ---------------- GroupNorm apply (bf16 out) ------------------------------------
__global__ __launch_bounds__(256) void gn_apply(const float* __restrict__ x,
                                                const float* __restrict__ w,
                                                const float* __restrict__ bsc) {
    int idx = blockIdx.x * 256 + threadIdx.x;
    int e   = idx * 4;
    int c   = (e / SEQ) & (CH - 1);
    int bg  = e >> 16;
    float mean = g_stats[bg * 2 + 0];
    float rstd = g_stats[bg * 2 + 1];
    float sw = w[c] * rstd;
    float sb = bsc[c] - mean * sw;
    float4 xv = ((const float4*)x)[idx];
    uint2 o;
    o.x = pack2(xv.y * sw + sb, xv.x * sw + sb);
    o.y = pack2(xv.w * sw + sb, xv.z * sw + sb);
    ((uint2*)g_hs)[idx] = o;
}

// ---------------- QKV GEMM (bf16 mma, cp.async double-buffered) -----------------
__global__ __launch_bounds__(256, 2) void qkv_mma(const float* __restrict__ bq,
                                                  const float* __restrict__ bkv) {
    int sb = blockIdx.x, jb = blockIdx.y, b = blockIdx.z;
    const __nv_bfloat16* A = g_wqkv + (size_t)jb * 128 * 512;
    const __nv_bfloat16* Bm = g_hs + (size_t)b * CH * SEQ + sb * 128;
    __nv_bfloat16* dst = (jb < 4) ? g_q : ((jb < 8) ? g_k : g_v);
    dst += (size_t)b * CH * SEQ;
    int jloc = (jb & 3) * 128;

    __shared__ __align__(16) __nv_bfloat16 As[2][128 * 40];
    __shared__ __align__(16) __nv_bfloat16 Bs[2][32 * 136];

    int tid = threadIdx.x, w = tid >> 5, lane = tid & 31;
    int u = lane & 3, g = lane >> 2, grp = lane >> 3, r = lane & 7;
    int wm = (w >> 2) * 64, wn = (w & 3) * 32;
    unsigned as0 = su32(As), bs0 = su32(Bs);

    int a_row = tid >> 1, a_c = (tid & 1) * 16;
    int b_row = tid >> 4, b_c = (tid & 15) * 8;

    float acc[4][4][4];
#pragma unroll
    for (int mt = 0; mt < 4; mt++)
#pragma unroll
        for (int nt = 0; nt < 4; nt++)
#pragma unroll
            for (int q = 0; q < 4; q++) acc[mt][nt][q] = 0.f;

    auto issue = [&](int it, int stg) {
        int kc = it * 32;
        unsigned ad = as0 + (stg * 5120 + a_row * 40 + a_c) * 2;
        cpa16(ad,      &A[(size_t)a_row * 512 + kc + a_c]);
        cpa16(ad + 16, &A[(size_t)a_row * 512 + kc + a_c + 8]);
        unsigned bd = bs0 + (stg * 4352 + b_row * 136 + b_c) * 2;
        cpa16(bd, &Bm[(size_t)(kc + b_row) * SEQ + b_c]);
        cpa16(bd + 16 * 136 * 2, &Bm[(size_t)(kc + b_row + 16) * SEQ + b_c]);
        cp_commit();
    };

    issue(0, 0);
    for (int it = 0; it < 16; it++) {
        int stg = it & 1;
        if (it < 15) { issue(it + 1, stg ^ 1); cp_wait<1>(); }
        else cp_wait<0>();
        __syncthreads();
#pragma unroll
        for (int ks = 0; ks < 32; ks += 16) {
            unsigned af[4][4], bf[4][2];
#pragma unroll
            for (int mt = 0; mt < 4; mt++) {
                unsigned ad = as0 + (stg * 5120 + (wm + mt * 16 + (grp & 1) * 8 + r) * 40 +
                                     ks + (grp >> 1) * 8) * 2;
                ldsm4(af[mt][0], af[mt][1], af[mt][2], af[mt][3], ad);
            }
#pragma unroll
            for (int ntp = 0; ntp < 2; ntp++) {
                unsigned bd = bs0 + (stg * 4352 + (ks + (grp & 1) * 8 + r) * 136 +
                                     wn + ntp * 16 + (grp >> 1) * 8) * 2;
                ldsm4t(bf[2 * ntp][0], bf[2 * ntp][1],
                       bf[2 * ntp + 1][0], bf[2 * ntp + 1][1], bd);
            }
#pragma unroll
            for (int mt = 0; mt < 4; mt++)
#pragma unroll
                for (int nt = 0; nt < 4; nt++)
                    mmabf(acc[mt][nt], af[mt][0], af[mt][1], af[mt][2], af[mt][3],
                          bf[nt][0], bf[nt][1]);
        }
        __syncthreads();
    }
    // epilogue
#pragma unroll
    for (int mt = 0; mt < 4; mt++) {
        int r0 = wm + mt * 16 + g;
        float bb0, bb1;
        if (jb < 4) { bb0 = bq[jloc + r0] * QS; bb1 = bq[jloc + r0 + 8] * QS; }
        else        { bb0 = bkv[(jb - 4) * 128 + r0]; bb1 = bkv[(jb - 4) * 128 + r0 + 8]; }
#pragma unroll
        for (int nt = 0; nt < 4; nt++) {
            int scol = sb * 128 + wn + nt * 8 + 2 * u;
            *(unsigned*)&dst[(size_t)(jloc + r0) * SEQ + scol] =
                pack2(acc[mt][nt][1] + bb0, acc[mt][nt][0] + bb0);
            *(unsigned*)&dst[(size_t)(jloc + r0 + 8) * SEQ + scol] =
                pack2(acc[mt][nt][3] + bb1, acc[mt][nt][2] + bb1);
        }
    }
}

// ---------------- Flash attention (bf16 mma, 3-stage cp.async, exp2) -------------
#define KVST (64 * 72)
#define ATTN_SMEM_BYTES ((64 * 136 + 6 * KVST) * 2)

__global__ __launch_bounds__(256, 2) void attn_mma() {
    int qb = blockIdx.x, bh = blockIdx.y;
    extern __shared__ __align__(16) __nv_bfloat16 SM[];
    __nv_bfloat16* Qs = SM;                    // [64][136]
    __nv_bfloat16* Kst = SM + 64 * 136;        // 3 stages [64][72]
    __nv_bfloat16* Vst = Kst + 3 * KVST;       // 3 stages [64][72]

    int tid = threadIdx.x, w = tid >> 5, lane = tid & 31;
    int u = lane & 3, g = lane >> 2, grp = lane >> 3, r = lane & 7;
    const __nv_bfloat16* qp = g_q + (size_t)bh * 64 * SEQ;
    const __nv_bfloat16* kp = g_k + (size_t)bh * 64 * SEQ;
    const __nv_bfloat16* vp = g_v + (size_t)bh * 64 * SEQ;
    int s0 = qb * 128;
    unsigned qs0 = su32(Qs), ks0 = su32(Kst), vs0 = su32(Vst);

    int ld_d = tid >> 2, ld_c = (tid & 3) * 16;

    auto issue_kv = [&](int kt, int stg) {
        int t0g = kt * 64;
        unsigned kd = ks0 + (stg * KVST + ld_d * 72 + ld_c) * 2;
        unsigned vd = vs0 + (stg * KVST + ld_d * 72 + ld_c) * 2;
        const __nv_bfloat16* kq = &kp[(size_t)ld_d * SEQ + t0g + ld_c];
        const __nv_bfloat16* vq = &vp[(size_t)ld_d * SEQ + t0g + ld_c];
        cpa16(kd, kq); cpa16(kd + 16, kq + 8);
        cpa16(vd, vq); cpa16(vd + 16, vq + 8);
        cp_commit();
    };

    issue_kv(0, 0);
    issue_kv(1, 1);

    // stage Q [64][128]
    for (int i = tid; i < 64 * 16; i += 256) {
        int d = i >> 4, c = (i & 15) * 8;
        *(uint4*)&Qs[d * 136 + c] = *(const uint4*)&qp[(size_t)d * SEQ + s0 + c];
    }
    __syncthreads();
    unsigned qa[4][4];
#pragma unroll
    for (int kd = 0; kd < 4; kd++) {
        unsigned ad = qs0 + ((kd * 16 + (grp >> 1) * 8 + r) * 136 +
                             w * 16 + (grp & 1) * 8) * 2;
        ldsm4t(qa[kd][0], qa[kd][1], qa[kd][2], qa[kd][3], ad);
    }

    float O[8][4];
#pragma unroll
    for (int nt = 0; nt < 8; nt++)
#pragma unroll
        for (int q = 0; q < 4; q++) O[nt][q] = 0.f;
    float m0 = -1e30f, m1 = -1e30f, l0 = 0.f, l1 = 0.f;

    int stg = 0, stg_nxt = 2;    // stage of tile kt; stage for tile kt+2
    for (int kt = 0; kt < 64; kt++) {
        if (kt < 63) cp_wait<1>(); else cp_wait<0>();
        __syncthreads();
        if (kt + 2 < 64) {
            issue_kv(kt + 2, stg_nxt);
            stg_nxt = (stg_nxt == 2) ? 0 : stg_nxt + 1;
        }

        // S = Q^T K
        float S[8][4];
#pragma unroll
        for (int nt = 0; nt < 8; nt++)
#pragma unroll
            for (int q = 0; q < 4; q++) S[nt][q] = 0.f;
#pragma unroll
        for (int kd = 0; kd < 4; kd++) {
#pragma unroll
            for (int ntp = 0; ntp < 4; ntp++) {
                unsigned kb0, kb1, kb2, kb3;
                unsigned ad = ks0 + (stg * KVST + (kd * 16 + (grp & 1) * 8 + r) * 72 +
                                     ntp * 16 + (grp >> 1) * 8) * 2;
                ldsm4t(kb0, kb1, kb2, kb3, ad);
                mmabf(S[2 * ntp], qa[kd][0], qa[kd][1], qa[kd][2], qa[kd][3], kb0, kb1);
                mmabf(S[2 * ntp + 1], qa[kd][0], qa[kd][1], qa[kd][2], qa[kd][3], kb2, kb3);
            }
        }

        // online softmax (base-2 domain; QS folded upstream)
        float rmax0 = -1e30f, rmax1 = -1e30f;
#pragma unroll
        for (int nt = 0; nt < 8; nt++) {
            rmax0 = fmaxf(rmax0, fmaxf(S[nt][0], S[nt][1]));
            rmax1 = fmaxf(rmax1, fmaxf(S[nt][2], S[nt][3]));
        }
        rmax0 = fmaxf(rmax0, __shfl_xor_sync(0xffffffffu, rmax0, 1));
        rmax0 = fmaxf(rmax0, __shfl_xor_sync(0xffffffffu, rmax0, 2));
        rmax1 = fmaxf(rmax1, __shfl_xor_sync(0xffffffffu, rmax1, 1));
        rmax1 = fmaxf(rmax1, __shfl_xor_sync(0xffffffffu, rmax1, 2));
        bool up = (rmax0 > m0) || (rmax1 > m1);
        if (__any_sync(0xffffffffu, up)) {
            float nm0 = fmaxf(m0, rmax0), nm1 = fmaxf(m1, rmax1);
            float al0 = exp2f(m0 - nm0), al1 = exp2f(m1 - nm1);
            l0 *= al0; l1 *= al1;
            m0 = nm0; m1 = nm1;
#pragma unroll
            for (int nt = 0; nt < 8; nt++) {
                O[nt][0] *= al0; O[nt][1] *= al0;
                O[nt][2] *= al1; O[nt][3] *= al1;
            }
        }
        float rs0 = 0.f, rs1 = 0.f;
#pragma unroll
        for (int nt = 0; nt < 8; nt++) {
            S[nt][0] = exp2f(S[nt][0] - m0);
            S[nt][1] = exp2f(S[nt][1] - m0);
            S[nt][2] = exp2f(S[nt][2] - m1);
            S[nt][3] = exp2f(S[nt][3] - m1);
            rs0 += S[nt][0] + S[nt][1];
            rs1 += S[nt][2] + S[nt][3];
        }
        rs0 += __shfl_xor_sync(0xffffffffu, rs0, 1);
        rs0 += __shfl_xor_sync(0xffffffffu, rs0, 2);
        rs1 += __shfl_xor_sync(0xffffffffu, rs1, 1);
        rs1 += __shfl_xor_sync(0xffffffffu, rs1, 2);
        l0 += rs0; l1 += rs1;

        // O += P V
#pragma unroll
        for (int kt4 = 0; kt4 < 4; kt4++) {
            unsigned pa0 = pack2(S[2 * kt4][1], S[2 * kt4][0]);
            unsigned pa1 = pack2(S[2 * kt4][3], S[2 * kt4][2]);
            unsigned pa2 = pack2(S[2 * kt4 + 1][1], S[2 * kt4 + 1][0]);
            unsigned pa3 = pack2(S[2 * kt4 + 1][3], S[2 * kt4 + 1][2]);
#pragma unroll
            for (int dp = 0; dp < 4; dp++) {
                unsigned vb0, vb1, vb2, vb3;
                unsigned ad = vs0 + (stg * KVST + (dp * 16 + (grp >> 1) * 8 + r) * 72 +
                                     kt4 * 16 + (grp & 1) * 8) * 2;
                ldsm4(vb0, vb1, vb2, vb3, ad);
                mmabf(O[2 * dp], pa0, pa1, pa2, pa3, vb0, vb1);
                mmabf(O[2 * dp + 1], pa0, pa1, pa2, pa3, vb2, vb3);
            }
        }
        stg = (stg == 2) ? 0 : stg + 1;
    }

    // epilogue: normalize, transpose via smem, write g_o[b][s][c]
    __syncthreads();
    __nv_bfloat16* Os = SM;       // [128 s][72 d]
    float inv0 = 1.f / l0, inv1 = 1.f / l1;
#pragma unroll
    for (int nt = 0; nt < 8; nt++) {
        int d0 = nt * 8 + 2 * u;
        *(unsigned*)&Os[(w * 16 + g) * 72 + d0] =
            pack2(O[nt][1] * inv0, O[nt][0] * inv0);
        *(unsigned*)&Os[(w * 16 + g + 8) * 72 + d0] =
            pack2(O[nt][3] * inv1, O[nt][2] * inv1);
    }
    __syncthreads();
    int b = bh >> 3, h = bh & 7;
    __nv_bfloat16* op = g_o + ((size_t)b * SEQ) * 512 + h * 64;
    for (int i = tid; i < 128 * 8; i += 256) {
        int row = i >> 3, c = (i & 7) * 8;
        *(uint4*)&op[(size_t)(s0 + row) * 512 + c] = *(const uint4*)&Os[row * 72 + c];
    }
}

// ---------------- Proj GEMM (bf16 mma, cp.async) + bias + residual ----------------
__global__ __launch_bounds__(256, 2) void proj_mma(const float* __restrict__ bproj,
                                                   const float* __restrict__ x,
                                                   float* __restrict__ out) {
    int sb = blockIdx.x, cb = blockIdx.y, b = blockIdx.z;
    const __nv_bfloat16* A = g_wproj + (size_t)cb * 128 * 512;
    const __nv_bfloat16* Bm = g_o + ((size_t)b * SEQ + sb * 128) * 512;

    __shared__ __align__(16) __nv_bfloat16 As[2][128 * 40];
    __shared__ __align__(16) __nv_bfloat16 Bs[2][128 * 40];

    int tid = threadIdx.x, w = tid >> 5, lane = tid & 31;
    int u = lane & 3, g = lane >> 2, grp = lane >> 3, r = lane & 7;
    int wm = (w >> 2) * 64, wn = (w & 3) * 32;
    unsigned as0 = su32(As), bs0 = su32(Bs);

    int t_row = tid >> 1, t_c = (tid & 1) * 16;

    float acc[4][4][4];
#pragma unroll
    for (int mt = 0; mt < 4; mt++)
#pragma unroll
        for (int nt = 0; nt < 4; nt++)
#pragma unroll
            for (int q = 0; q < 4; q++) acc[mt][nt][q] = 0.f;

    auto issue = [&](int it, int stg) {
        int kc = it * 32;
        unsigned ad = as0 + (stg * 5120 + t_row * 40 + t_c) * 2;
        unsigned bd = bs0 + (stg * 5120 + t_row * 40 + t_c) * 2;
        cpa16(ad,      &A[(size_t)t_row * 512 + kc + t_c]);
        cpa16(ad + 16, &A[(size_t)t_row * 512 + kc + t_c + 8]);
        cpa16(bd,      &Bm[(size_t)t_row * 512 + kc + t_c]);
        cpa16(bd + 16, &Bm[(size_t)t_row * 512 + kc + t_c + 8]);
        cp_commit();
    };

    issue(0, 0);
    for (int it = 0; it < 16; it++) {
        int stg = it & 1;
        if (it < 15) { issue(it + 1, stg ^ 1); cp_wait<1>(); }
        else cp_wait<0>();
        __syncthreads();
#pragma unroll
        for (int ks = 0; ks < 32; ks += 16) {
            unsigned af[4][4], bf[4][2];
#pragma unroll
            for (int mt = 0; mt < 4; mt++) {
                unsigned ad = as0 + (stg * 5120 + (wm + mt * 16 + (grp & 1) * 8 + r) * 40 +
                                     ks + (grp >> 1) * 8) * 2;
                ldsm4(af[mt][0], af[mt][1], af[mt][2], af[mt][3], ad);
            }
#pragma unroll
            for (int ntp = 0; ntp < 2; ntp++) {
                unsigned bd = bs0 + (stg * 5120 + (wn + ntp * 16 + (grp >> 1) * 8 + r) * 40 +
                                     ks + (grp & 1) * 8) * 2;
                ldsm4(bf[2 * ntp][0], bf[2 * ntp][1],
                      bf[2 * ntp + 1][0], bf[2 * ntp + 1][1], bd);
            }
#pragma unroll
            for (int mt = 0; mt < 4; mt++)
#pragma unroll
                for (int nt = 0; nt < 4; nt++)
                    mmabf(acc[mt][nt], af[mt][0], af[mt][1], af[mt][2], af[mt][3],
                          bf[nt][0], bf[nt][1]);
        }
        __syncthreads();
    }
    // epilogue: + bias + residual, fp32 out [b][c][s]
#pragma unroll
    for (int mt = 0; mt < 4; mt++) {
        int cc0 = cb * 128 + wm + mt * 16 + g;
        float bb0 = bproj[cc0], bb1 = bproj[cc0 + 8];
#pragma unroll
        for (int nt = 0; nt < 4; nt++) {
            int scol = sb * 128 + wn + nt * 8 + 2 * u;
            size_t off0 = ((size_t)b * CH + cc0) * SEQ + scol;
            size_t off1 = ((size_t)b * CH + cc0 + 8) * SEQ + scol;
            float2 x0 = *(const float2*)&x[off0];
            float2 x1 = *(const float2*)&x[off1];
            float2 o0, o1;
            o0.x = acc[mt][nt][0] + bb0 + x0.x;
            o0.y = acc[mt][nt][1] + bb0 + x0.y;
            o1.x = acc[mt][nt][2] + bb1 + x1.x;
            o1.y = acc[mt][nt][3] + bb1 + x1.y;
            *(float2*)&out[off0] = o0;
            *(float2*)&out[off1] = o1;
        }
    }
}

// ---------------- launch ----------------------------------------------------------
extern "C" void kernel_launch(void* const* d_in, const int* in_sizes, int n_in,
                              void* d_out, int out_size) {
    const float* x     = (const float*)d_in[0];
    const float* gnw   = (const float*)d_in[1];
    const float* gnb   = (const float*)d_in[2];
    const float* wq    = (const float*)d_in[3];
    const float* bq    = (const float*)d_in[4];
    const float* wkv   = (const float*)d_in[5];
    const float* bkv   = (const float*)d_in[6];
    const float* wproj = (const float*)d_in[7];
    const float* bproj = (const float*)d_in[8];
    float* out = (float*)d_out;

    cudaFuncSetAttribute(attn_mma, cudaFuncAttributeMaxDynamicSharedMemorySize,
                         ATTN_SMEM_BYTES);

    cvt_weights<<<2048, 256>>>(wq, wkv, wproj);
    gn_partial<<<512, 256>>>(x);
    gn_finalize<<<1, 64>>>();
    gn_apply<<<4096, 256>>>(x, gnw, gnb);
    qkv_mma<<<dim3(32, 12, NB), 256>>>(bq, bkv);
    attn_mma<<<dim3(32, 16), 256, ATTN_SMEM_BYTES>>>();
    proj_mma<<<dim3(32, 4, NB), 256>>>(bproj, x, out);
}

// round 7
// speedup vs baseline: 8.9798x; 1.0593x over previous
#include <cuda_runtime.h>
#include <cuda_bf16.h>
#include <math.h>

#define SEQ 4096
#define CH  512
#define NB  2
#define QS  0.18033688011112042f   // 0.125 * log2(e)

// ---------------- scratch (bf16) --------------------------------------------
__device__ __nv_bfloat16 g_hs[NB * CH * SEQ];      // [b][c][s]
__device__ __nv_bfloat16 g_q [NB * CH * SEQ];      // [b][h*64+d][s], wq pre-scaled QS
__device__ __nv_bfloat16 g_k [NB * CH * SEQ];
__device__ __nv_bfloat16 g_v [NB * CH * SEQ];
__device__ __nv_bfloat16 g_o [NB * SEQ * CH];      // [b][s][c]  (attention out)
__device__ __nv_bfloat16 g_wqkv[1536 * 512];       // rows 0-511 wq*QS, 512-1535 wkv
__device__ __nv_bfloat16 g_wproj[512 * 512];
__device__ float g_sums[64 * 8 * 2];

// ---------------- helpers ----------------------------------------------------
__device__ __forceinline__ unsigned su32(const void* p) {
    return (unsigned)__cvta_generic_to_shared(p);
}
__device__ __forceinline__ void ldsm4(unsigned& a, unsigned& b, unsigned& c,
                                      unsigned& d, unsigned addr) {
    asm volatile("ldmatrix.sync.aligned.m8n8.x4.shared.b16 {%0,%1,%2,%3},[%4];"
                 : "=r"(a), "=r"(b), "=r"(c), "=r"(d) : "r"(addr));
}
__device__ __forceinline__ void ldsm4t(unsigned& a, unsigned& b, unsigned& c,
                                       unsigned& d, unsigned addr) {
    asm volatile("ldmatrix.sync.aligned.m8n8.x4.trans.shared.b16 {%0,%1,%2,%3},[%4];"
                 : "=r"(a), "=r"(b), "=r"(c), "=r"(d) : "r"(addr));
}
__device__ __forceinline__ void mmabf(float c[4], unsigned a0, unsigned a1,
                                      unsigned a2, unsigned a3,
                                      unsigned b0, unsigned b1) {
    asm volatile(
        "mma.sync.aligned.m16n8k16.row.col.f32.bf16.bf16.f32 "
        "{%0,%1,%2,%3},{%4,%5,%6,%7},{%8,%9},{%0,%1,%2,%3};"
        : "+f"(c[0]), "+f"(c[1]), "+f"(c[2]), "+f"(c[3])
        : "r"(a0), "r"(a1), "r"(a2), "r"(a3), "r"(b0), "r"(b1));
}
__device__ __forceinline__ unsigned pack2(float hi, float lo) {
    unsigned d;
    asm("cvt.rn.bf16x2.f32 %0,%1,%2;" : "=r"(d) : "f"(hi), "f"(lo));
    return d;
}
__device__ __forceinline__ void cpa16(unsigned dst, const void* src) {
    asm volatile("cp.async.cg.shared.global [%0], [%1], 16;" :: "r"(dst), "l"(src));
}
__device__ __forceinline__ void cp_commit() {
    asm volatile("cp.async.commit_group;");
}
template <int N> __device__ __forceinline__ void cp_wait() {
    asm volatile("cp.async.wait_group %0;" :: "n"(N));
}

// ---------------- prep: GN partial stats + weight conversion (merged) ----------
__global__ __launch_bounds__(256) void prep(const float* __restrict__ x,
                                            const float* __restrict__ wq,
                                            const float* __restrict__ wkv,
                                            const float* __restrict__ wproj) {
    int blk = blockIdx.x;
    int tid = threadIdx.x;
    if (blk < 512) {
        int bg = blk >> 3, chunk = blk & 7;
        const float4* p = (const float4*)(x + (size_t)bg * 65536 + chunk * 8192);
        float s = 0.f, s2 = 0.f;
#pragma unroll
        for (int j = 0; j < 8; j++) {
            float4 v = p[tid + j * 256];
            s  += v.x + v.y + v.z + v.w;
            s2 += v.x * v.x + v.y * v.y + v.z * v.z + v.w * v.w;
        }
        __shared__ float ss[256], sq[256];
        ss[tid] = s; sq[tid] = s2;
        __syncthreads();
        for (int st = 128; st > 0; st >>= 1) {
            if (tid < st) { ss[tid] += ss[tid + st]; sq[tid] += sq[tid + st]; }
            __syncthreads();
        }
        if (tid == 0) {
            g_sums[blk * 2 + 0] = ss[0];
            g_sums[blk * 2 + 1] = sq[0];
        }
    } else {
        int i = (blk - 512) * 256 + tid;          // 0..524287
        g_wqkv[262144 + i] = __float2bfloat16_rn(wkv[i]);
        if (i < 262144) {
            g_wqkv[i]  = __float2bfloat16_rn(wq[i] * QS);
            g_wproj[i] = __float2bfloat16_rn(wproj[i]);
        }
    }
}

// ---------------- GroupNorm apply (bf16 out), stats finalized in-block ----------
__global__ __launch_bounds__(256) void gn_apply(const float* __restrict__ x,
                                                const float* __restrict__ w,
                                                const float* __restrict__ bsc) {
    int idx = blockIdx.x * 256 + threadIdx.x;
    int e   = idx * 4;
    int c   = (e / SEQ) & (CH - 1);
    int bg  = e >> 16;                  // one bg per block (1024 elems < 16*4096)
    __shared__ float st[2];
    if (threadIdx.x == 0) {
        float s = 0.f, s2 = 0.f;
#pragma unroll
        for (int c8 = 0; c8 < 8; c8++) {
            s  += g_sums[(bg * 8 + c8) * 2 + 0];
            s2 += g_sums[(bg * 8 + c8) * 2 + 1];
        }
        float inv_n = 1.0f / 65536.0f;
        float mean = s * inv_n;
        float var  = s2 * inv_n - mean * mean;
        st[0] = mean;
        st[1] = rsqrtf(var + 1e-5f);
    }
    __syncthreads();
    float sw = w[c] * st[1];
    float sb = bsc[c] - st[0] * sw;
    float4 xv = ((const float4*)x)[idx];
    uint2 o;
    o.x = pack2(xv.y * sw + sb, xv.x * sw + sb);
    o.y = pack2(xv.w * sw + sb, xv.z * sw + sb);
    ((uint2*)g_hs)[idx] = o;
}

// ---------------- QKV GEMM (bf16 mma, 3-stage cp.async, 1 sync/iter) ------------
#define QKV_ASTG 5120
#define QKV_BSTG 4352
#define QKV_SMEM_BYTES ((3 * QKV_ASTG + 3 * QKV_BSTG) * 2)

__global__ __launch_bounds__(256, 2) void qkv_mma(const float* __restrict__ bq,
                                                  const float* __restrict__ bkv) {
    int sb = blockIdx.x, jb = blockIdx.y, b = blockIdx.z;
    const __nv_bfloat16* A = g_wqkv + (size_t)jb * 128 * 512;
    const __nv_bfloat16* Bm = g_hs + (size_t)b * CH * SEQ + sb * 128;
    __nv_bfloat16* dst = (jb < 4) ? g_q : ((jb < 8) ? g_k : g_v);
    dst += (size_t)b * CH * SEQ;
    int jloc = (jb & 3) * 128;

    extern __shared__ __align__(16) __nv_bfloat16 SMQ[];
    unsigned as0 = su32(SMQ), bs0 = as0 + 3 * QKV_ASTG * 2;

    int tid = threadIdx.x, w = tid >> 5, lane = tid & 31;
    int u = lane & 3, g = lane >> 2, grp = lane >> 3, r = lane & 7;
    int wm = (w >> 2) * 64, wn = (w & 3) * 32;

    int a_row = tid >> 1, a_c = (tid & 1) * 16;
    int b_row = tid >> 4, b_c = (tid & 15) * 8;

    float acc[4][4][4];
#pragma unroll
    for (int mt = 0; mt < 4; mt++)
#pragma unroll
        for (int nt = 0; nt < 4; nt++)
#pragma unroll
            for (int q = 0; q < 4; q++) acc[mt][nt][q] = 0.f;

    auto issue = [&](int it, int stg) {
        int kc = it * 32;
        unsigned ad = as0 + (stg * QKV_ASTG + a_row * 40 + a_c) * 2;
        cpa16(ad,      &A[(size_t)a_row * 512 + kc + a_c]);
        cpa16(ad + 16, &A[(size_t)a_row * 512 + kc + a_c + 8]);
        unsigned bd = bs0 + (stg * QKV_BSTG + b_row * 136 + b_c) * 2;
        cpa16(bd, &Bm[(size_t)(kc + b_row) * SEQ + b_c]);
        cpa16(bd + 16 * 136 * 2, &Bm[(size_t)(kc + b_row + 16) * SEQ + b_c]);
        cp_commit();
    };

    issue(0, 0); issue(1, 1);
    for (int it = 0; it < 16; it++) {
        int stg = it % 3;
        if (it < 15) cp_wait<1>(); else cp_wait<0>();
        __syncthreads();
        if (it + 2 < 16) issue(it + 2, (it + 2) % 3);
#pragma unroll
        for (int ks = 0; ks < 32; ks += 16) {
            unsigned af[4][4], bf[4][2];
#pragma unroll
            for (int mt = 0; mt < 4; mt++) {
                unsigned ad = as0 + (stg * QKV_ASTG + (wm + mt * 16 + (grp & 1) * 8 + r) * 40 +
                                     ks + (grp >> 1) * 8) * 2;
                ldsm4(af[mt][0], af[mt][1], af[mt][2], af[mt][3], ad);
            }
#pragma unroll
            for (int ntp = 0; ntp < 2; ntp++) {
                unsigned bd = bs0 + (stg * QKV_BSTG + (ks + (grp & 1) * 8 + r) * 136 +
                                     wn + ntp * 16 + (grp >> 1) * 8) * 2;
                ldsm4t(bf[2 * ntp][0], bf[2 * ntp][1],
                       bf[2 * ntp + 1][0], bf[2 * ntp + 1][1], bd);
            }
#pragma unroll
            for (int mt = 0; mt < 4; mt++)
#pragma unroll
                for (int nt = 0; nt < 4; nt++)
                    mmabf(acc[mt][nt], af[mt][0], af[mt][1], af[mt][2], af[mt][3],
                          bf[nt][0], bf[nt][1]);
        }
    }
    // epilogue
#pragma unroll
    for (int mt = 0; mt < 4; mt++) {
        int r0 = wm + mt * 16 + g;
        float bb0, bb1;
        if (jb < 4) { bb0 = bq[jloc + r0] * QS; bb1 = bq[jloc + r0 + 8] * QS; }
        else        { bb0 = bkv[(jb - 4) * 128 + r0]; bb1 = bkv[(jb - 4) * 128 + r0 + 8]; }
#pragma unroll
        for (int nt = 0; nt < 4; nt++) {
            int scol = sb * 128 + wn + nt * 8 + 2 * u;
            *(unsigned*)&dst[(size_t)(jloc + r0) * SEQ + scol] =
                pack2(acc[mt][nt][1] + bb0, acc[mt][nt][0] + bb0);
            *(unsigned*)&dst[(size_t)(jloc + r0 + 8) * SEQ + scol] =
                pack2(acc[mt][nt][3] + bb1, acc[mt][nt][2] + bb1);
        }
    }
}

// ---------------- Flash attention (bf16 mma, 3-stage cp.async, exp2) -------------
#define KVST (64 * 72)
#define ATTN_SMEM_BYTES ((64 * 136 + 6 * KVST) * 2)

__global__ __launch_bounds__(256, 2) void attn_mma() {
    int qb = blockIdx.x, bh = blockIdx.y;
    extern __shared__ __align__(16) __nv_bfloat16 SM[];
    __nv_bfloat16* Qs = SM;                    // [64][136]
    __nv_bfloat16* Kst = SM + 64 * 136;        // 3 stages [64][72]
    __nv_bfloat16* Vst = Kst + 3 * KVST;       // 3 stages [64][72]

    int tid = threadIdx.x, w = tid >> 5, lane = tid & 31;
    int u = lane & 3, g = lane >> 2, grp = lane >> 3, r = lane & 7;
    const __nv_bfloat16* qp = g_q + (size_t)bh * 64 * SEQ;
    const __nv_bfloat16* kp = g_k + (size_t)bh * 64 * SEQ;
    const __nv_bfloat16* vp = g_v + (size_t)bh * 64 * SEQ;
    int s0 = qb * 128;
    unsigned qs0 = su32(Qs), ks0 = su32(Kst), vs0 = su32(Vst);

    int ld_d = tid >> 2, ld_c = (tid & 3) * 16;

    auto issue_kv = [&](int kt, int stg) {
        int t0g = kt * 64;
        unsigned kd = ks0 + (stg * KVST + ld_d * 72 + ld_c) * 2;
        unsigned vd = vs0 + (stg * KVST + ld_d * 72 + ld_c) * 2;
        const __nv_bfloat16* kq = &kp[(size_t)ld_d * SEQ + t0g + ld_c];
        const __nv_bfloat16* vq = &vp[(size_t)ld_d * SEQ + t0g + ld_c];
        cpa16(kd, kq); cpa16(kd + 16, kq + 8);
        cpa16(vd, vq); cpa16(vd + 16, vq + 8);
        cp_commit();
    };

    issue_kv(0, 0);
    issue_kv(1, 1);

    // stage Q [64][128]
    for (int i = tid; i < 64 * 16; i += 256) {
        int d = i >> 4, c = (i & 15) * 8;
        *(uint4*)&Qs[d * 136 + c] = *(const uint4*)&qp[(size_t)d * SEQ + s0 + c];
    }
    __syncthreads();
    unsigned qa[4][4];
#pragma unroll
    for (int kd = 0; kd < 4; kd++) {
        unsigned ad = qs0 + ((kd * 16 + (grp >> 1) * 8 + r) * 136 +
                             w * 16 + (grp & 1) * 8) * 2;
        ldsm4t(qa[kd][0], qa[kd][1], qa[kd][2], qa[kd][3], ad);
    }

    float O[8][4];
#pragma unroll
    for (int nt = 0; nt < 8; nt++)
#pragma unroll
        for (int q = 0; q < 4; q++) O[nt][q] = 0.f;
    float m0 = -1e30f, m1 = -1e30f, l0 = 0.f, l1 = 0.f;   // l: per-lane partials

    int stg = 0, stg_nxt = 2;
    for (int kt = 0; kt < 64; kt++) {
        if (kt < 63) cp_wait<1>(); else cp_wait<0>();
        __syncthreads();
        if (kt + 2 < 64) {
            issue_kv(kt + 2, stg_nxt);
            stg_nxt = (stg_nxt == 2) ? 0 : stg_nxt + 1;
        }

        // S = Q^T K
        float S[8][4];
#pragma unroll
        for (int nt = 0; nt < 8; nt++)
#pragma unroll
            for (int q = 0; q < 4; q++) S[nt][q] = 0.f;
#pragma unroll
        for (int kd = 0; kd < 4; kd++) {
#pragma unroll
            for (int ntp = 0; ntp < 4; ntp++) {
                unsigned kb0, kb1, kb2, kb3;
                unsigned ad = ks0 + (stg * KVST + (kd * 16 + (grp & 1) * 8 + r) * 72 +
                                     ntp * 16 + (grp >> 1) * 8) * 2;
                ldsm4t(kb0, kb1, kb2, kb3, ad);
                mmabf(S[2 * ntp], qa[kd][0], qa[kd][1], qa[kd][2], qa[kd][3], kb0, kb1);
                mmabf(S[2 * ntp + 1], qa[kd][0], qa[kd][1], qa[kd][2], qa[kd][3], kb2, kb3);
            }
        }

        // online softmax (base-2 domain); l kept as per-lane partials
        float rmax0 = -1e30f, rmax1 = -1e30f;
#pragma unroll
        for (int nt = 0; nt < 8; nt++) {
            rmax0 = fmaxf(rmax0, fmaxf(S[nt][0], S[nt][1]));
            rmax1 = fmaxf(rmax1, fmaxf(S[nt][2], S[nt][3]));
        }
        rmax0 = fmaxf(rmax0, __shfl_xor_sync(0xffffffffu, rmax0, 1));
        rmax0 = fmaxf(rmax0, __shfl_xor_sync(0xffffffffu, rmax0, 2));
        rmax1 = fmaxf(rmax1, __shfl_xor_sync(0xffffffffu, rmax1, 1));
        rmax1 = fmaxf(rmax1, __shfl_xor_sync(0xffffffffu, rmax1, 2));
        bool up = (rmax0 > m0) || (rmax1 > m1);
        if (__any_sync(0xffffffffu, up)) {
            float nm0 = fmaxf(m0, rmax0), nm1 = fmaxf(m1, rmax1);
            float al0 = exp2f(m0 - nm0), al1 = exp2f(m1 - nm1);
            l0 *= al0; l1 *= al1;
            m0 = nm0; m1 = nm1;
#pragma unroll
            for (int nt = 0; nt < 8; nt++) {
                O[nt][0] *= al0; O[nt][1] *= al0;
                O[nt][2] *= al1; O[nt][3] *= al1;
            }
        }
#pragma unroll
        for (int nt = 0; nt < 8; nt++) {
            S[nt][0] = exp2f(S[nt][0] - m0);
            S[nt][1] = exp2f(S[nt][1] - m0);
            S[nt][2] = exp2f(S[nt][2] - m1);
            S[nt][3] = exp2f(S[nt][3] - m1);
            l0 += S[nt][0] + S[nt][1];
            l1 += S[nt][2] + S[nt][3];
        }

        // O += P V
#pragma unroll
        for (int kt4 = 0; kt4 < 4; kt4++) {
            unsigned pa0 = pack2(S[2 * kt4][1], S[2 * kt4][0]);
            unsigned pa1 = pack2(S[2 * kt4][3], S[2 * kt4][2]);
            unsigned pa2 = pack2(S[2 * kt4 + 1][1], S[2 * kt4 + 1][0]);
            unsigned pa3 = pack2(S[2 * kt4 + 1][3], S[2 * kt4 + 1][2]);
#pragma unroll
            for (int dp = 0; dp < 4; dp++) {
                unsigned vb0, vb1, vb2, vb3;
                unsigned ad = vs0 + (stg * KVST + (dp * 16 + (grp >> 1) * 8 + r) * 72 +
                                     kt4 * 16 + (grp & 1) * 8) * 2;
                ldsm4(vb0, vb1, vb2, vb3, ad);
                mmabf(O[2 * dp], pa0, pa1, pa2, pa3, vb0, vb1);
                mmabf(O[2 * dp + 1], pa0, pa1, pa2, pa3, vb2, vb3);
            }
        }
        stg = (stg == 2) ? 0 : stg + 1;
    }

    // cross-lane l reduction (once)
    l0 += __shfl_xor_sync(0xffffffffu, l0, 1);
    l0 += __shfl_xor_sync(0xffffffffu, l0, 2);
    l1 += __shfl_xor_sync(0xffffffffu, l1, 1);
    l1 += __shfl_xor_sync(0xffffffffu, l1, 2);

    // epilogue: normalize, transpose via smem, write g_o[b][s][c]
    __syncthreads();
    __nv_bfloat16* Os = SM;       // [128 s][72 d]
    float inv0 = 1.f / l0, inv1 = 1.f / l1;
#pragma unroll
    for (int nt = 0; nt < 8; nt++) {
        int d0 = nt * 8 + 2 * u;
        *(unsigned*)&Os[(w * 16 + g) * 72 + d0] =
            pack2(O[nt][1] * inv0, O[nt][0] * inv0);
        *(unsigned*)&Os[(w * 16 + g + 8) * 72 + d0] =
            pack2(O[nt][3] * inv1, O[nt][2] * inv1);
    }
    __syncthreads();
    int b = bh >> 3, h = bh & 7;
    __nv_bfloat16* op = g_o + ((size_t)b * SEQ) * 512 + h * 64;
    for (int i = tid; i < 128 * 8; i += 256) {
        int row = i >> 3, c = (i & 7) * 8;
        *(uint4*)&op[(size_t)(s0 + row) * 512 + c] = *(const uint4*)&Os[row * 72 + c];
    }
}

// ---------------- Proj GEMM (bf16 mma, 3-stage cp.async) + bias + residual -------
#define PRJ_STG 5120
#define PRJ_SMEM_BYTES (6 * PRJ_STG * 2)

__global__ __launch_bounds__(256, 2) void proj_mma(const float* __restrict__ bproj,
                                                   const float* __restrict__ x,
                                                   float* __restrict__ out) {
    int sb = blockIdx.x, cb = blockIdx.y, b = blockIdx.z;
    const __nv_bfloat16* A = g_wproj + (size_t)cb * 128 * 512;
    const __nv_bfloat16* Bm = g_o + ((size_t)b * SEQ + sb * 128) * 512;

    extern __shared__ __align__(16) __nv_bfloat16 SMP[];
    unsigned as0 = su32(SMP), bs0 = as0 + 3 * PRJ_STG * 2;

    int tid = threadIdx.x, w = tid >> 5, lane = tid & 31;
    int u = lane & 3, g = lane >> 2, grp = lane >> 3, r = lane & 7;
    int wm = (w >> 2) * 64, wn = (w & 3) * 32;

    int t_row = tid >> 1, t_c = (tid & 1) * 16;

    float acc[4][4][4];
#pragma unroll
    for (int mt = 0; mt < 4; mt++)
#pragma unroll
        for (int nt = 0; nt < 4; nt++)
#pragma unroll
            for (int q = 0; q < 4; q++) acc[mt][nt][q] = 0.f;

    auto issue = [&](int it, int stg) {
        int kc = it * 32;
        unsigned ad = as0 + (stg * PRJ_STG + t_row * 40 + t_c) * 2;
        unsigned bd = bs0 + (stg * PRJ_STG + t_row * 40 + t_c) * 2;
        cpa16(ad,      &A[(size_t)t_row * 512 + kc + t_c]);
        cpa16(ad + 16, &A[(size_t)t_row * 512 + kc + t_c + 8]);
        cpa16(bd,      &Bm[(size_t)t_row * 512 + kc + t_c]);
        cpa16(bd + 16, &Bm[(size_t)t_row * 512 + kc + t_c + 8]);
        cp_commit();
    };

    issue(0, 0); issue(1, 1);
    for (int it = 0; it < 16; it++) {
        int stg = it % 3;
        if (it < 15) cp_wait<1>(); else cp_wait<0>();
        __syncthreads();
        if (it + 2 < 16) issue(it + 2, (it + 2) % 3);
#pragma unroll
        for (int ks = 0; ks < 32; ks += 16) {
            unsigned af[4][4], bf[4][2];
#pragma unroll
            for (int mt = 0; mt < 4; mt++) {
                unsigned ad = as0 + (stg * PRJ_STG + (wm + mt * 16 + (grp & 1) * 8 + r) * 40 +
                                     ks + (grp >> 1) * 8) * 2;
                ldsm4(af[mt][0], af[mt][1], af[mt][2], af[mt][3], ad);
            }
#pragma unroll
            for (int ntp = 0; ntp < 2; ntp++) {
                unsigned bd = bs0 + (stg * PRJ_STG + (wn + ntp * 16 + (grp >> 1) * 8 + r) * 40 +
                                     ks + (grp & 1) * 8) * 2;
                ldsm4(bf[2 * ntp][0], bf[2 * ntp][1],
                      bf[2 * ntp + 1][0], bf[2 * ntp + 1][1], bd);
            }
#pragma unroll
            for (int mt = 0; mt < 4; mt++)
#pragma unroll
                for (int nt = 0; nt < 4; nt++)
                    mmabf(acc[mt][nt], af[mt][0], af[mt][1], af[mt][2], af[mt][3],
                          bf[nt][0], bf[nt][1]);
        }
    }
    // epilogue: + bias + residual, fp32 out [b][c][s]
#pragma unroll
    for (int mt = 0; mt < 4; mt++) {
        int cc0 = cb * 128 + wm + mt * 16 + g;
        float bb0 = bproj[cc0], bb1 = bproj[cc0 + 8];
#pragma unroll
        for (int nt = 0; nt < 4; nt++) {
            int scol = sb * 128 + wn + nt * 8 + 2 * u;
            size_t off0 = ((size_t)b * CH + cc0) * SEQ + scol;
            size_t off1 = ((size_t)b * CH + cc0 + 8) * SEQ + scol;
            float2 x0 = *(const float2*)&x[off0];
            float2 x1 = *(const float2*)&x[off1];
            float2 o0, o1;
            o0.x = acc[mt][nt][0] + bb0 + x0.x;
            o0.y = acc[mt][nt][1] + bb0 + x0.y;
            o1.x = acc[mt][nt][2] + bb1 + x1.x;
            o1.y = acc[mt][nt][3] + bb1 + x1.y;
            *(float2*)&out[off0] = o0;
            *(float2*)&out[off1] = o1;
        }
    }
}

// ---------------- launch ----------------------------------------------------------
extern "C" void kernel_launch(void* const* d_in, const int* in_sizes, int n_in,
                              void* d_out, int out_size) {
    const float* x     = (const float*)d_in[0];
    const float* gnw   = (const float*)d_in[1];
    const float* gnb   = (const float*)d_in[2];
    const float* wq    = (const float*)d_in[3];
    const float* bq    = (const float*)d_in[4];
    const float* wkv   = (const float*)d_in[5];
    const float* bkv   = (const float*)d_in[6];
    const float* wproj = (const float*)d_in[7];
    const float* bproj = (const float*)d_in[8];
    float* out = (float*)d_out;

    cudaFuncSetAttribute(attn_mma, cudaFuncAttributeMaxDynamicSharedMemorySize,
                         ATTN_SMEM_BYTES);
    cudaFuncSetAttribute(qkv_mma, cudaFuncAttributeMaxDynamicSharedMemorySize,
                         QKV_SMEM_BYTES);
    cudaFuncSetAttribute(proj_mma, cudaFuncAttributeMaxDynamicSharedMemorySize,
                         PRJ_SMEM_BYTES);

    prep<<<2560, 256>>>(x, wq, wkv, wproj);
    gn_apply<<<4096, 256>>>(x, gnw, gnb);
    qkv_mma<<<dim3(32, 12, NB), 256, QKV_SMEM_BYTES>>>(bq, bkv);
    attn_mma<<<dim3(32, 16), 256, ATTN_SMEM_BYTES>>>();
    proj_mma<<<dim3(32, 4, NB), 256, PRJ_SMEM_BYTES>>>(bproj, x, out);
}

// round 8
// speedup vs baseline: 9.3683x; 1.0433x over previous
#include <cuda_runtime.h>
#include <cuda_bf16.h>
#include <cuda_fp16.h>
#include <math.h>

#define SEQ 4096
#define CH  512
#define NB  2
#define QS  0.18033688011112042f   // 0.125 * log2(e)

// ---------------- scratch ------------------------------------------------------
__device__ __nv_bfloat16 g_hs[NB * CH * SEQ];      // [b][c][s]
__device__ __nv_bfloat16 g_q [NB * CH * SEQ];      // [b][h*64+d][s], wq pre-scaled QS
__device__ __nv_bfloat16 g_k [NB * CH * SEQ];
__device__ __half        g_v [NB * CH * SEQ];      // fp16 V for f16 PV mma
__device__ __nv_bfloat16 g_o [NB * SEQ * CH];      // [b][s][c]  (attention out)
__device__ __nv_bfloat16 g_wqkv[1536 * 512];       // rows 0-511 wq*QS, 512-1535 wkv
__device__ __nv_bfloat16 g_wproj[512 * 512];
__device__ float g_sums[64 * 8 * 2];

// ---------------- helpers ----------------------------------------------------
__device__ __forceinline__ unsigned su32(const void* p) {
    return (unsigned)__cvta_generic_to_shared(p);
}
__device__ __forceinline__ void ldsm4(unsigned& a, unsigned& b, unsigned& c,
                                      unsigned& d, unsigned addr) {
    asm volatile("ldmatrix.sync.aligned.m8n8.x4.shared.b16 {%0,%1,%2,%3},[%4];"
                 : "=r"(a), "=r"(b), "=r"(c), "=r"(d) : "r"(addr));
}
__device__ __forceinline__ void ldsm4t(unsigned& a, unsigned& b, unsigned& c,
                                       unsigned& d, unsigned addr) {
    asm volatile("ldmatrix.sync.aligned.m8n8.x4.trans.shared.b16 {%0,%1,%2,%3},[%4];"
                 : "=r"(a), "=r"(b), "=r"(c), "=r"(d) : "r"(addr));
}
__device__ __forceinline__ void mmabf(float c[4], unsigned a0, unsigned a1,
                                      unsigned a2, unsigned a3,
                                      unsigned b0, unsigned b1) {
    asm volatile(
        "mma.sync.aligned.m16n8k16.row.col.f32.bf16.bf16.f32 "
        "{%0,%1,%2,%3},{%4,%5,%6,%7},{%8,%9},{%0,%1,%2,%3};"
        : "+f"(c[0]), "+f"(c[1]), "+f"(c[2]), "+f"(c[3])
        : "r"(a0), "r"(a1), "r"(a2), "r"(a3), "r"(b0), "r"(b1));
}
__device__ __forceinline__ void mmahf(float c[4], unsigned a0, unsigned a1,
                                      unsigned a2, unsigned a3,
                                      unsigned b0, unsigned b1) {
    asm volatile(
        "mma.sync.aligned.m16n8k16.row.col.f32.f16.f16.f32 "
        "{%0,%1,%2,%3},{%4,%5,%6,%7},{%8,%9},{%0,%1,%2,%3};"
        : "+f"(c[0]), "+f"(c[1]), "+f"(c[2]), "+f"(c[3])
        : "r"(a0), "r"(a1), "r"(a2), "r"(a3), "r"(b0), "r"(b1));
}
__device__ __forceinline__ unsigned pack2(float hi, float lo) {
    unsigned d;
    asm("cvt.rn.bf16x2.f32 %0,%1,%2;" : "=r"(d) : "f"(hi), "f"(lo));
    return d;
}
__device__ __forceinline__ unsigned pack2h(float hi, float lo) {
    unsigned d;
    asm("cvt.rn.f16x2.f32 %0,%1,%2;" : "=r"(d) : "f"(hi), "f"(lo));
    return d;
}
__device__ __forceinline__ unsigned ex2h2(unsigned x) {
    unsigned d;
    asm("ex2.approx.f16x2 %0,%1;" : "=r"(d) : "r"(x));
    return d;
}
__device__ __forceinline__ void cpa16(unsigned dst, const void* src) {
    asm volatile("cp.async.cg.shared.global [%0], [%1], 16;" :: "r"(dst), "l"(src));
}
__device__ __forceinline__ void cp_commit() {
    asm volatile("cp.async.commit_group;");
}
template <int N> __device__ __forceinline__ void cp_wait() {
    asm volatile("cp.async.wait_group %0;" :: "n"(N));
}

// ---------------- prep: GN partial stats + weight conversion (merged) ----------
__global__ __launch_bounds__(256) void prep(const float* __restrict__ x,
                                            const float* __restrict__ wq,
                                            const float* __restrict__ wkv,
                                            const float* __restrict__ wproj) {
    int blk = blockIdx.x;
    int tid = threadIdx.x;
    if (blk < 512) {
        int bg = blk >> 3, chunk = blk & 7;
        const float4* p = (const float4*)(x + (size_t)bg * 65536 + chunk * 8192);
        float s = 0.f, s2 = 0.f;
#pragma unroll
        for (int j = 0; j < 8; j++) {
            float4 v = p[tid + j * 256];
            s  += v.x + v.y + v.z + v.w;
            s2 += v.x * v.x + v.y * v.y + v.z * v.z + v.w * v.w;
        }
        __shared__ float ss[256], sq[256];
        ss[tid] = s; sq[tid] = s2;
        __syncthreads();
        for (int st = 128; st > 0; st >>= 1) {
            if (tid < st) { ss[tid] += ss[tid + st]; sq[tid] += sq[tid + st]; }
            __syncthreads();
        }
        if (tid == 0) {
            g_sums[blk * 2 + 0] = ss[0];
            g_sums[blk * 2 + 1] = sq[0];
        }
    } else {
        int i = (blk - 512) * 256 + tid;          // 0..524287
        g_wqkv[262144 + i] = __float2bfloat16_rn(wkv[i]);
        if (i < 262144) {
            g_wqkv[i]  = __float2bfloat16_rn(wq[i] * QS);
            g_wproj[i] = __float2bfloat16_rn(wproj[i]);
        }
    }
}

// ---------------- GroupNorm apply (bf16 out), stats finalized in-block ----------
__global__ __launch_bounds__(256) void gn_apply(const float* __restrict__ x,
                                                const float* __restrict__ w,
                                                const float* __restrict__ bsc) {
    int idx = blockIdx.x * 256 + threadIdx.x;
    int e   = idx * 4;
    int c   = (e / SEQ) & (CH - 1);
    int bg  = e >> 16;
    __shared__ float st[2];
    if (threadIdx.x == 0) {
        float s = 0.f, s2 = 0.f;
#pragma unroll
        for (int c8 = 0; c8 < 8; c8++) {
            s  += g_sums[(bg * 8 + c8) * 2 + 0];
            s2 += g_sums[(bg * 8 + c8) * 2 + 1];
        }
        float inv_n = 1.0f / 65536.0f;
        float mean = s * inv_n;
        float var  = s2 * inv_n - mean * mean;
        st[0] = mean;
        st[1] = rsqrtf(var + 1e-5f);
    }
    __syncthreads();
    float sw = w[c] * st[1];
    float sb = bsc[c] - st[0] * sw;
    float4 xv = ((const float4*)x)[idx];
    uint2 o;
    o.x = pack2(xv.y * sw + sb, xv.x * sw + sb);
    o.y = pack2(xv.w * sw + sb, xv.z * sw + sb);
    ((uint2*)g_hs)[idx] = o;
}

// ---------------- QKV GEMM (bf16 mma, 3-stage cp.async, 1 sync/iter) ------------
#define QKV_ASTG 5120
#define QKV_BSTG 4352
#define QKV_SMEM_BYTES ((3 * QKV_ASTG + 3 * QKV_BSTG) * 2)

__global__ __launch_bounds__(256, 2) void qkv_mma(const float* __restrict__ bq,
                                                  const float* __restrict__ bkv) {
    int sb = blockIdx.x, jb = blockIdx.y, b = blockIdx.z;
    const __nv_bfloat16* A = g_wqkv + (size_t)jb * 128 * 512;
    const __nv_bfloat16* Bm = g_hs + (size_t)b * CH * SEQ + sb * 128;
    int jloc = (jb & 3) * 128;

    extern __shared__ __align__(16) __nv_bfloat16 SMQ[];
    unsigned as0 = su32(SMQ), bs0 = as0 + 3 * QKV_ASTG * 2;

    int tid = threadIdx.x, w = tid >> 5, lane = tid & 31;
    int u = lane & 3, g = lane >> 2, grp = lane >> 3, r = lane & 7;
    int wm = (w >> 2) * 64, wn = (w & 3) * 32;

    int a_row = tid >> 1, a_c = (tid & 1) * 16;
    int b_row = tid >> 4, b_c = (tid & 15) * 8;

    float acc[4][4][4];
#pragma unroll
    for (int mt = 0; mt < 4; mt++)
#pragma unroll
        for (int nt = 0; nt < 4; nt++)
#pragma unroll
            for (int q = 0; q < 4; q++) acc[mt][nt][q] = 0.f;

    auto issue = [&](int it, int stg) {
        int kc = it * 32;
        unsigned ad = as0 + (stg * QKV_ASTG + a_row * 40 + a_c) * 2;
        cpa16(ad,      &A[(size_t)a_row * 512 + kc + a_c]);
        cpa16(ad + 16, &A[(size_t)a_row * 512 + kc + a_c + 8]);
        unsigned bd = bs0 + (stg * QKV_BSTG + b_row * 136 + b_c) * 2;
        cpa16(bd, &Bm[(size_t)(kc + b_row) * SEQ + b_c]);
        cpa16(bd + 16 * 136 * 2, &Bm[(size_t)(kc + b_row + 16) * SEQ + b_c]);
        cp_commit();
    };

    issue(0, 0); issue(1, 1);
    for (int it = 0; it < 16; it++) {
        int stg = it % 3;
        if (it < 15) cp_wait<1>(); else cp_wait<0>();
        __syncthreads();
        if (it + 2 < 16) issue(it + 2, (it + 2) % 3);
#pragma unroll
        for (int ks = 0; ks < 32; ks += 16) {
            unsigned af[4][4], bf[4][2];
#pragma unroll
            for (int mt = 0; mt < 4; mt++) {
                unsigned ad = as0 + (stg * QKV_ASTG + (wm + mt * 16 + (grp & 1) * 8 + r) * 40 +
                                     ks + (grp >> 1) * 8) * 2;
                ldsm4(af[mt][0], af[mt][1], af[mt][2], af[mt][3], ad);
            }
#pragma unroll
            for (int ntp = 0; ntp < 2; ntp++) {
                unsigned bd = bs0 + (stg * QKV_BSTG + (ks + (grp & 1) * 8 + r) * 136 +
                                     wn + ntp * 16 + (grp >> 1) * 8) * 2;
                ldsm4t(bf[2 * ntp][0], bf[2 * ntp][1],
                       bf[2 * ntp + 1][0], bf[2 * ntp + 1][1], bd);
            }
#pragma unroll
            for (int mt = 0; mt < 4; mt++)
#pragma unroll
                for (int nt = 0; nt < 4; nt++)
                    mmabf(acc[mt][nt], af[mt][0], af[mt][1], af[mt][2], af[mt][3],
                          bf[nt][0], bf[nt][1]);
        }
    }
    // epilogue: Q/K -> bf16, V -> fp16
#pragma unroll
    for (int mt = 0; mt < 4; mt++) {
        int r0 = wm + mt * 16 + g;
        float bb0, bb1;
        if (jb < 4) { bb0 = bq[jloc + r0] * QS; bb1 = bq[jloc + r0 + 8] * QS; }
        else        { bb0 = bkv[(jb - 4) * 128 + r0]; bb1 = bkv[(jb - 4) * 128 + r0 + 8]; }
#pragma unroll
        for (int nt = 0; nt < 4; nt++) {
            int scol = sb * 128 + wn + nt * 8 + 2 * u;
            if (jb < 8) {
                __nv_bfloat16* dst = ((jb < 4) ? g_q : g_k) + (size_t)b * CH * SEQ;
                *(unsigned*)&dst[(size_t)(jloc + r0) * SEQ + scol] =
                    pack2(acc[mt][nt][1] + bb0, acc[mt][nt][0] + bb0);
                *(unsigned*)&dst[(size_t)(jloc + r0 + 8) * SEQ + scol] =
                    pack2(acc[mt][nt][3] + bb1, acc[mt][nt][2] + bb1);
            } else {
                __half* dst = g_v + (size_t)b * CH * SEQ;
                *(unsigned*)&dst[(size_t)(jloc + r0) * SEQ + scol] =
                    pack2h(acc[mt][nt][1] + bb0, acc[mt][nt][0] + bb0);
                *(unsigned*)&dst[(size_t)(jloc + r0 + 8) * SEQ + scol] =
                    pack2h(acc[mt][nt][3] + bb1, acc[mt][nt][2] + bb1);
            }
        }
    }
}

// ---------------- Flash attention (bf16 QK, f16 PV, l-via-MMA) ------------------
#define KVST (64 * 72)
#define ATTN_SMEM_BYTES ((64 * 136 + 6 * KVST) * 2)
#define HONES 0x3C003C00u   // f16x2 (1.0, 1.0)

__global__ __launch_bounds__(256, 2) void attn_mma() {
    int qb = blockIdx.x, bh = blockIdx.y;
    extern __shared__ __align__(16) __nv_bfloat16 SM[];
    __nv_bfloat16* Qs = SM;                    // [64][136]
    __nv_bfloat16* Kst = SM + 64 * 136;        // 3 stages [64][72]
    __half*        Vst = (__half*)(Kst + 3 * KVST);  // 3 stages [64][72]

    int tid = threadIdx.x, w = tid >> 5, lane = tid & 31;
    int u = lane & 3, g = lane >> 2, grp = lane >> 3, r = lane & 7;
    const __nv_bfloat16* qp = g_q + (size_t)bh * 64 * SEQ;
    const __nv_bfloat16* kp = g_k + (size_t)bh * 64 * SEQ;
    const __half*        vp = g_v + (size_t)bh * 64 * SEQ;
    int s0 = qb * 128;
    unsigned qs0 = su32(Qs), ks0 = su32(Kst), vs0 = su32(Vst);

    int ld_d = tid >> 2, ld_c = (tid & 3) * 16;

    auto issue_kv = [&](int kt, int stg) {
        int t0g = kt * 64;
        unsigned kd = ks0 + (stg * KVST + ld_d * 72 + ld_c) * 2;
        unsigned vd = vs0 + (stg * KVST + ld_d * 72 + ld_c) * 2;
        const __nv_bfloat16* kq = &kp[(size_t)ld_d * SEQ + t0g + ld_c];
        const __half*        vq = &vp[(size_t)ld_d * SEQ + t0g + ld_c];
        cpa16(kd, kq); cpa16(kd + 16, kq + 8);
        cpa16(vd, vq); cpa16(vd + 16, vq + 8);
        cp_commit();
    };

    issue_kv(0, 0);
    issue_kv(1, 1);

    // stage Q [64][128]
    for (int i = tid; i < 64 * 16; i += 256) {
        int d = i >> 4, c = (i & 15) * 8;
        *(uint4*)&Qs[d * 136 + c] = *(const uint4*)&qp[(size_t)d * SEQ + s0 + c];
    }
    __syncthreads();
    unsigned qa[4][4];
#pragma unroll
    for (int kd = 0; kd < 4; kd++) {
        unsigned ad = qs0 + ((kd * 16 + (grp >> 1) * 8 + r) * 136 +
                             w * 16 + (grp & 1) * 8) * 2;
        ldsm4t(qa[kd][0], qa[kd][1], qa[kd][2], qa[kd][3], ad);
    }

    float O[8][4], Lacc[4];
#pragma unroll
    for (int nt = 0; nt < 8; nt++)
#pragma unroll
        for (int q = 0; q < 4; q++) O[nt][q] = 0.f;
#pragma unroll
    for (int q = 0; q < 4; q++) Lacc[q] = 0.f;
    float m0 = -1e30f, m1 = -1e30f;

    int stg = 0, stg_nxt = 2;
    for (int kt = 0; kt < 64; kt++) {
        if (kt < 63) cp_wait<1>(); else cp_wait<0>();
        __syncthreads();
        if (kt + 2 < 64) {
            issue_kv(kt + 2, stg_nxt);
            stg_nxt = (stg_nxt == 2) ? 0 : stg_nxt + 1;
        }

        // S = Q^T K  (bf16)
        float S[8][4];
#pragma unroll
        for (int nt = 0; nt < 8; nt++)
#pragma unroll
            for (int q = 0; q < 4; q++) S[nt][q] = 0.f;
#pragma unroll
        for (int kd = 0; kd < 4; kd++) {
#pragma unroll
            for (int ntp = 0; ntp < 4; ntp++) {
                unsigned kb0, kb1, kb2, kb3;
                unsigned ad = ks0 + (stg * KVST + (kd * 16 + (grp & 1) * 8 + r) * 72 +
                                     ntp * 16 + (grp >> 1) * 8) * 2;
                ldsm4t(kb0, kb1, kb2, kb3, ad);
                mmabf(S[2 * ntp], qa[kd][0], qa[kd][1], qa[kd][2], qa[kd][3], kb0, kb1);
                mmabf(S[2 * ntp + 1], qa[kd][0], qa[kd][1], qa[kd][2], qa[kd][3], kb2, kb3);
            }
        }

        // online softmax (base-2); P computed as f16x2 via ex2.approx.f16x2
        float rmax0 = -1e30f, rmax1 = -1e30f;
#pragma unroll
        for (int nt = 0; nt < 8; nt++) {
            rmax0 = fmaxf(rmax0, fmaxf(S[nt][0], S[nt][1]));
            rmax1 = fmaxf(rmax1, fmaxf(S[nt][2], S[nt][3]));
        }
        rmax0 = fmaxf(rmax0, __shfl_xor_sync(0xffffffffu, rmax0, 1));
        rmax0 = fmaxf(rmax0, __shfl_xor_sync(0xffffffffu, rmax0, 2));
        rmax1 = fmaxf(rmax1, __shfl_xor_sync(0xffffffffu, rmax1, 1));
        rmax1 = fmaxf(rmax1, __shfl_xor_sync(0xffffffffu, rmax1, 2));
        bool up = (rmax0 > m0) || (rmax1 > m1);
        if (__any_sync(0xffffffffu, up)) {
            float nm0 = fmaxf(m0, rmax0), nm1 = fmaxf(m1, rmax1);
            float al0 = exp2f(m0 - nm0), al1 = exp2f(m1 - nm1);
            Lacc[0] *= al0; Lacc[1] *= al0; Lacc[2] *= al1; Lacc[3] *= al1;
            m0 = nm0; m1 = nm1;
#pragma unroll
            for (int nt = 0; nt < 8; nt++) {
                O[nt][0] *= al0; O[nt][1] *= al0;
                O[nt][2] *= al1; O[nt][3] *= al1;
            }
        }
        unsigned Plo[8], Phi[8];
#pragma unroll
        for (int nt = 0; nt < 8; nt++) {
            Plo[nt] = ex2h2(pack2h(S[nt][1] - m0, S[nt][0] - m0));
            Phi[nt] = ex2h2(pack2h(S[nt][3] - m1, S[nt][2] - m1));
        }

        // O += P V  (f16);  Lacc += P * ones
#pragma unroll
        for (int kt4 = 0; kt4 < 4; kt4++) {
            unsigned pa0 = Plo[2 * kt4], pa1 = Phi[2 * kt4];
            unsigned pa2 = Plo[2 * kt4 + 1], pa3 = Phi[2 * kt4 + 1];
            mmahf(Lacc, pa0, pa1, pa2, pa3, HONES, HONES);
#pragma unroll
            for (int dp = 0; dp < 4; dp++) {
                unsigned vb0, vb1, vb2, vb3;
                unsigned ad = vs0 + (stg * KVST + (dp * 16 + (grp >> 1) * 8 + r) * 72 +
                                     kt4 * 16 + (grp & 1) * 8) * 2;
                ldsm4(vb0, vb1, vb2, vb3, ad);
                mmahf(O[2 * dp], pa0, pa1, pa2, pa3, vb0, vb1);
                mmahf(O[2 * dp + 1], pa0, pa1, pa2, pa3, vb2, vb3);
            }
        }
        stg = (stg == 2) ? 0 : stg + 1;
    }

    // epilogue: normalize (l = Lacc, identical across quad lanes), transpose, store
    __syncthreads();
    __nv_bfloat16* Os = SM;       // [128 s][72 d]
    float inv0 = 1.f / Lacc[0], inv1 = 1.f / Lacc[2];
#pragma unroll
    for (int nt = 0; nt < 8; nt++) {
        int d0 = nt * 8 + 2 * u;
        *(unsigned*)&Os[(w * 16 + g) * 72 + d0] =
            pack2(O[nt][1] * inv0, O[nt][0] * inv0);
        *(unsigned*)&Os[(w * 16 + g + 8) * 72 + d0] =
            pack2(O[nt][3] * inv1, O[nt][2] * inv1);
    }
    __syncthreads();
    int b = bh >> 3, h = bh & 7;
    __nv_bfloat16* op = g_o + ((size_t)b * SEQ) * 512 + h * 64;
    for (int i = tid; i < 128 * 8; i += 256) {
        int row = i >> 3, c = (i & 7) * 8;
        *(uint4*)&op[(size_t)(s0 + row) * 512 + c] = *(const uint4*)&Os[row * 72 + c];
    }
}

// ---------------- Proj GEMM (bf16 mma, 3-stage cp.async) + bias + residual -------
#define PRJ_STG 5120
#define PRJ_SMEM_BYTES (6 * PRJ_STG * 2)

__global__ __launch_bounds__(256, 2) void proj_mma(const float* __restrict__ bproj,
                                                   const float* __restrict__ x,
                                                   float* __restrict__ out) {
    int sb = blockIdx.x, cb = blockIdx.y, b = blockIdx.z;
    const __nv_bfloat16* A = g_wproj + (size_t)cb * 128 * 512;
    const __nv_bfloat16* Bm = g_o + ((size_t)b * SEQ + sb * 128) * 512;

    extern __shared__ __align__(16) __nv_bfloat16 SMP[];
    unsigned as0 = su32(SMP), bs0 = as0 + 3 * PRJ_STG * 2;

    int tid = threadIdx.x, w = tid >> 5, lane = tid & 31;
    int u = lane & 3, g = lane >> 2, grp = lane >> 3, r = lane & 7;
    int wm = (w >> 2) * 64, wn = (w & 3) * 32;

    int t_row = tid >> 1, t_c = (tid & 1) * 16;

    float acc[4][4][4];
#pragma unroll
    for (int mt = 0; mt < 4; mt++)
#pragma unroll
        for (int nt = 0; nt < 4; nt++)
#pragma unroll
            for (int q = 0; q < 4; q++) acc[mt][nt][q] = 0.f;

    auto issue = [&](int it, int stg) {
        int kc = it * 32;
        unsigned ad = as0 + (stg * PRJ_STG + t_row * 40 + t_c) * 2;
        unsigned bd = bs0 + (stg * PRJ_STG + t_row * 40 + t_c) * 2;
        cpa16(ad,      &A[(size_t)t_row * 512 + kc + t_c]);
        cpa16(ad + 16, &A[(size_t)t_row * 512 + kc + t_c + 8]);
        cpa16(bd,      &Bm[(size_t)t_row * 512 + kc + t_c]);
        cpa16(bd + 16, &Bm[(size_t)t_row * 512 + kc + t_c + 8]);
        cp_commit();
    };

    issue(0, 0); issue(1, 1);
    for (int it = 0; it < 16; it++) {
        int stg = it % 3;
        if (it < 15) cp_wait<1>(); else cp_wait<0>();
        __syncthreads();
        if (it + 2 < 16) issue(it + 2, (it + 2) % 3);
#pragma unroll
        for (int ks = 0; ks < 32; ks += 16) {
            unsigned af[4][4], bf[4][2];
#pragma unroll
            for (int mt = 0; mt < 4; mt++) {
                unsigned ad = as0 + (stg * PRJ_STG + (wm + mt * 16 + (grp & 1) * 8 + r) * 40 +
                                     ks + (grp >> 1) * 8) * 2;
                ldsm4(af[mt][0], af[mt][1], af[mt][2], af[mt][3], ad);
            }
#pragma unroll
            for (int ntp = 0; ntp < 2; ntp++) {
                unsigned bd = bs0 + (stg * PRJ_STG + (wn + ntp * 16 + (grp >> 1) * 8 + r) * 40 +
                                     ks + (grp & 1) * 8) * 2;
                ldsm4(bf[2 * ntp][0], bf[2 * ntp][1],
                      bf[2 * ntp + 1][0], bf[2 * ntp + 1][1], bd);
            }
#pragma unroll
            for (int mt = 0; mt < 4; mt++)
#pragma unroll
                for (int nt = 0; nt < 4; nt++)
                    mmabf(acc[mt][nt], af[mt][0], af[mt][1], af[mt][2], af[mt][3],
                          bf[nt][0], bf[nt][1]);
        }
    }
    // epilogue: + bias + residual, fp32 out [b][c][s]
#pragma unroll
    for (int mt = 0; mt < 4; mt++) {
        int cc0 = cb * 128 + wm + mt * 16 + g;
        float bb0 = bproj[cc0], bb1 = bproj[cc0 + 8];
#pragma unroll
        for (int nt = 0; nt < 4; nt++) {
            int scol = sb * 128 + wn + nt * 8 + 2 * u;
            size_t off0 = ((size_t)b * CH + cc0) * SEQ + scol;
            size_t off1 = ((size_t)b * CH + cc0 + 8) * SEQ + scol;
            float2 x0 = *(const float2*)&x[off0];
            float2 x1 = *(const float2*)&x[off1];
            float2 o0, o1;
            o0.x = acc[mt][nt][0] + bb0 + x0.x;
            o0.y = acc[mt][nt][1] + bb0 + x0.y;
            o1.x = acc[mt][nt][2] + bb1 + x1.x;
            o1.y = acc[mt][nt][3] + bb1 + x1.y;
            *(float2*)&out[off0] = o0;
            *(float2*)&out[off1] = o1;
        }
    }
}

// ---------------- launch ----------------------------------------------------------
extern "C" void kernel_launch(void* const* d_in, const int* in_sizes, int n_in,
                              void* d_out, int out_size) {
    const float* x     = (const float*)d_in[0];
    const float* gnw   = (const float*)d_in[1];
    const float* gnb   = (const float*)d_in[2];
    const float* wq    = (const float*)d_in[3];
    const float* bq    = (const float*)d_in[4];
    const float* wkv   = (const float*)d_in[5];
    const float* bkv   = (const float*)d_in[6];
    const float* wproj = (const float*)d_in[7];
    const float* bproj = (const float*)d_in[8];
    float* out = (float*)d_out;

    cudaFuncSetAttribute(attn_mma, cudaFuncAttributeMaxDynamicSharedMemorySize,
                         ATTN_SMEM_BYTES);
    cudaFuncSetAttribute(qkv_mma, cudaFuncAttributeMaxDynamicSharedMemorySize,
                         QKV_SMEM_BYTES);
    cudaFuncSetAttribute(proj_mma, cudaFuncAttributeMaxDynamicSharedMemorySize,
                         PRJ_SMEM_BYTES);

    prep<<<2560, 256>>>(x, wq, wkv, wproj);
    gn_apply<<<4096, 256>>>(x, gnw, gnb);
    qkv_mma<<<dim3(32, 12, NB), 256, QKV_SMEM_BYTES>>>(bq, bkv);
    attn_mma<<<dim3(32, 16), 256, ATTN_SMEM_BYTES>>>();
    proj_mma<<<dim3(32, 4, NB), 256, PRJ_SMEM_BYTES>>>(bproj, x, out);
}